// round 1
// baseline (speedup 1.0000x reference)
#include <cuda_runtime.h>
#include <math.h>

// ---------------- problem constants ----------------
#define B_   4
#define S_   4096
#define D_   512
#define H_   8
#define W_   32
#define HD_  64
#define NW_  (S_ / W_)        // 128
#define M_   (B_ * S_)        // 16384
#define GS_  128              // global strided seq len
#define GM_  (B_ * GS_)       // 512

// ---------------- scratch (no allocations allowed) ----------------
__device__ float g_xl  [M_ * D_];
__device__ float g_xg  [M_ * D_];
__device__ float g_tmp [M_ * D_];
__device__ float g_tmp2[M_ * D_];
__device__ float g_qkv [M_ * 3 * D_];
__device__ float g_hid [M_ * 4 * D_];
__device__ float g_xs  [GM_ * D_];
__device__ float g_atts[GM_ * D_];
__device__ float g_ps  [GM_ * D_];

// ---------------- helpers ----------------
__device__ __forceinline__ float blk_reduce_sum(float v, float* red) {
    int lane = threadIdx.x & 31, w = threadIdx.x >> 5;
    #pragma unroll
    for (int o = 16; o; o >>= 1) v += __shfl_xor_sync(0xffffffffu, v, o);
    if (lane == 0) red[w] = v;
    __syncthreads();
    int nw = blockDim.x >> 5;
    if (w == 0) {
        float t = (lane < nw) ? red[lane] : 0.f;
        #pragma unroll
        for (int o = 16; o; o >>= 1) t += __shfl_xor_sync(0xffffffffu, t, o);
        if (lane == 0) red[0] = t;
    }
    __syncthreads();
    float r = red[0];
    __syncthreads();
    return r;
}

__device__ __forceinline__ float blk_reduce_max(float v, float* red) {
    int lane = threadIdx.x & 31, w = threadIdx.x >> 5;
    #pragma unroll
    for (int o = 16; o; o >>= 1) v = fmaxf(v, __shfl_xor_sync(0xffffffffu, v, o));
    if (lane == 0) red[w] = v;
    __syncthreads();
    int nw = blockDim.x >> 5;
    if (w == 0) {
        float t = (lane < nw) ? red[lane] : -1e30f;
        #pragma unroll
        for (int o = 16; o; o >>= 1) t = fmaxf(t, __shfl_xor_sync(0xffffffffu, t, o));
        if (lane == 0) red[0] = t;
    }
    __syncthreads();
    float r = red[0];
    __syncthreads();
    return r;
}

__device__ __forceinline__ float gelu_tanh(float x) {
    float x3 = x * x * x;
    return 0.5f * x * (1.f + tanhf(0.7978845608028654f * (x + 0.044715f * x3)));
}

// ---------------- GEMM: C[M,N] = act(A[M,K] @ W[K,N] + bias[N]) ----------------
// Tiles: BM=BN=128, BK=8, 256 threads, 8x8 per thread. Requires M%128==N%128==0, K%8==0.
__global__ void __launch_bounds__(256, 2) gemm_kernel(
    const float* __restrict__ A, const float* __restrict__ Wm,
    const float* __restrict__ bias, float* __restrict__ C,
    int M, int K, int N, int act)
{
    __shared__ float As[8][128];
    __shared__ float Bs[8][128];
    int tid = threadIdx.x;
    int bm = blockIdx.y * 128;
    int bn = blockIdx.x * 128;
    int tx = tid & 15, ty = tid >> 4;

    int arow = (tid * 4) >> 3;   // 0..127
    int acol = (tid * 4) & 7;    // 0 or 4
    int brow = (tid * 4) >> 7;   // 0..7
    int bcol = (tid * 4) & 127;

    float acc[8][8];
    #pragma unroll
    for (int i = 0; i < 8; i++)
        #pragma unroll
        for (int j = 0; j < 8; j++) acc[i][j] = 0.f;

    const float* Aptr = A + (size_t)(bm + arow) * K + acol;
    const float* Bptr = Wm + (size_t)brow * N + bn + bcol;

    for (int k0 = 0; k0 < K; k0 += 8) {
        float4 a4 = *(const float4*)(Aptr + k0);
        As[acol + 0][arow] = a4.x;
        As[acol + 1][arow] = a4.y;
        As[acol + 2][arow] = a4.z;
        As[acol + 3][arow] = a4.w;
        float4 b4 = *(const float4*)(Bptr + (size_t)k0 * N);
        *(float4*)&Bs[brow][bcol] = b4;
        __syncthreads();
        #pragma unroll
        for (int k = 0; k < 8; k++) {
            float4 a0 = *(const float4*)&As[k][ty * 8];
            float4 a1 = *(const float4*)&As[k][ty * 8 + 4];
            float4 b0 = *(const float4*)&Bs[k][tx * 8];
            float4 b1 = *(const float4*)&Bs[k][tx * 8 + 4];
            float ar[8] = {a0.x, a0.y, a0.z, a0.w, a1.x, a1.y, a1.z, a1.w};
            float br[8] = {b0.x, b0.y, b0.z, b0.w, b1.x, b1.y, b1.z, b1.w};
            #pragma unroll
            for (int i = 0; i < 8; i++)
                #pragma unroll
                for (int j = 0; j < 8; j++)
                    acc[i][j] += ar[i] * br[j];
        }
        __syncthreads();
    }

    #pragma unroll
    for (int i = 0; i < 8; i++) {
        int row = bm + ty * 8 + i;
        #pragma unroll
        for (int j = 0; j < 8; j += 4) {
            int col = bn + tx * 8 + j;
            float4 r;
            float* rv = &r.x;
            #pragma unroll
            for (int jj = 0; jj < 4; jj++) {
                float v = acc[i][j + jj] + bias[col + jj];
                if (act == 1) v = gelu_tanh(v);
                rv[jj] = v;
            }
            *(float4*)&C[(size_t)row * N + col] = r;
        }
    }
}

static inline void gemm(const float* A, const float* W, const float* bias, float* C,
                        int M, int K, int N, int act) {
    dim3 grid(N / 128, M / 128);
    gemm_kernel<<<grid, 256>>>(A, W, bias, C, M, K, N, act);
}

// ---------------- local windowed attention ----------------
// grid: B*NW*H blocks, 32 threads. qkv: (B,S,3,H,HD). out: (B,S,D) pre-proj.
__global__ void local_attn_kernel(const float* __restrict__ qkv,
                                  const float* __restrict__ rel,
                                  float* __restrict__ out)
{
    int blk = blockIdx.x;
    int h   = blk & (H_ - 1);
    int win = (blk >> 3) & (NW_ - 1);
    int b   = blk >> 10;  // /(8*128)
    int s0  = win * W_;
    int tid = threadIdx.x;

    __shared__ float ks[W_][HD_];
    __shared__ float vs[W_][HD_];

    size_t base = ((size_t)(b * S_ + s0)) * 1536 + h * HD_;
    for (int idx = tid; idx < W_ * HD_; idx += 32) {
        int j = idx >> 6, d = idx & 63;
        ks[j][d] = qkv[base + (size_t)j * 1536 + 512 + d];
        vs[j][d] = qkv[base + (size_t)j * 1536 + 1024 + d];
    }
    __syncthreads();

    float q[HD_];
    {
        const float* qr = qkv + base + (size_t)tid * 1536;
        #pragma unroll
        for (int d = 0; d < HD_; d++) q[d] = qr[d];
    }

    float sc[W_];
    float m = -1e30f;
    #pragma unroll
    for (int j = 0; j < W_; j++) {
        float a = 0.f;
        const float4* kj = (const float4*)ks[j];
        #pragma unroll
        for (int d4 = 0; d4 < HD_ / 4; d4++) {
            float4 kk = kj[d4];
            a += q[4 * d4 + 0] * kk.x + q[4 * d4 + 1] * kk.y
               + q[4 * d4 + 2] * kk.z + q[4 * d4 + 3] * kk.w;
        }
        a = a * 0.125f + rel[(tid - j + W_ - 1) * H_ + h];
        sc[j] = a;
        m = fmaxf(m, a);
    }
    float sum = 0.f;
    #pragma unroll
    for (int j = 0; j < W_; j++) { sc[j] = expf(sc[j] - m); sum += sc[j]; }
    float inv = 1.f / sum;

    float o[HD_];
    #pragma unroll
    for (int d = 0; d < HD_; d++) o[d] = 0.f;
    #pragma unroll
    for (int j = 0; j < W_; j++) {
        float p = sc[j];
        const float4* vj = (const float4*)vs[j];
        #pragma unroll
        for (int d4 = 0; d4 < HD_ / 4; d4++) {
            float4 vv = vj[d4];
            o[4 * d4 + 0] += p * vv.x;
            o[4 * d4 + 1] += p * vv.y;
            o[4 * d4 + 2] += p * vv.z;
            o[4 * d4 + 3] += p * vv.w;
        }
    }
    float* orow = out + (size_t)(b * S_ + s0 + tid) * D_ + h * HD_;
    #pragma unroll
    for (int d = 0; d < HD_; d++) orow[d] = o[d] * inv;
}

// ---------------- global attention (128-token strided sequence) ----------------
// grid: B*H*GS_ blocks (one query each), 128 threads. qkv: (B,GS,3,H,HD). out: (B,GS,D).
__global__ void gattn_kernel(const float* __restrict__ qkv, float* __restrict__ out)
{
    int blk = blockIdx.x;
    int i = blk & (GS_ - 1);
    int h = (blk >> 7) & (H_ - 1);
    int b = blk >> 10;
    int tid = threadIdx.x;

    __shared__ float q[HD_];
    __shared__ float p[GS_];
    __shared__ float red[32];

    if (tid < HD_) q[tid] = qkv[(size_t)(b * GS_ + i) * 1536 + h * HD_ + tid];
    __syncthreads();

    // thread tid = key index
    float s;
    {
        const float* krow = qkv + (size_t)(b * GS_ + tid) * 1536 + 512 + h * HD_;
        float a = 0.f;
        #pragma unroll
        for (int d = 0; d < HD_; d++) a += q[d] * krow[d];
        s = a * 0.125f;
    }
    float m = blk_reduce_max(s, red);
    float e = expf(s - m);
    float sum = blk_reduce_sum(e, red);
    p[tid] = e;
    __syncthreads();

    if (tid < HD_) {
        float a = 0.f;
        for (int j = 0; j < GS_; j++)
            a += p[j] * qkv[(size_t)(b * GS_ + j) * 1536 + 1024 + h * HD_ + tid];
        out[(size_t)(b * GS_ + i) * D_ + h * HD_ + tid] = a / sum;
    }
}

// ---------------- fused residual add + LayerNorm ----------------
// one block per row, 128 threads, D=512 (4 per thread). out may alias x.
__global__ void add_ln_kernel(const float* __restrict__ x, const float* __restrict__ a,
                              const float* __restrict__ g, const float* __restrict__ bb,
                              float* __restrict__ out)
{
    __shared__ float red[32];
    size_t row = blockIdx.x;
    const float* xr = x + row * D_;
    const float* ar = a + row * D_;
    float v[4];
    float s = 0.f;
    #pragma unroll
    for (int i = 0; i < 4; i++) {
        int c = threadIdx.x + i * 128;
        v[i] = xr[c] + ar[c];
        s += v[i];
    }
    s = blk_reduce_sum(s, red);
    float mu = s * (1.f / D_);
    float s2 = 0.f;
    #pragma unroll
    for (int i = 0; i < 4; i++) { float d = v[i] - mu; s2 += d * d; }
    s2 = blk_reduce_sum(s2, red);
    float rstd = rsqrtf(s2 * (1.f / D_) + 1e-5f);
    #pragma unroll
    for (int i = 0; i < 4; i++) {
        int c = threadIdx.x + i * 128;
        out[row * D_ + c] = (v[i] - mu) * rstd * g[c] + bb[c];
    }
}

// ---------------- depthwise conv (K=7, same padding) + residual ----------------
__global__ void dwconv_kernel(const float* __restrict__ x, const float* __restrict__ w,
                              const float* __restrict__ cb, float* __restrict__ y)
{
    int idx = blockIdx.x * blockDim.x + threadIdx.x;
    if (idx >= M_ * D_) return;
    int d = idx & (D_ - 1);
    int s = (idx >> 9) & (S_ - 1);
    int b = idx >> 21;
    float acc = x[idx] + cb[d];
    #pragma unroll
    for (int k = 0; k < 7; k++) {
        int ss = s + k - 3;
        if (ss >= 0 && ss < S_)
            acc += w[d * 7 + k] * x[((size_t)(b * S_ + ss) << 9) + d];
    }
    y[idx] = acc;
}

// ---------------- strided gather (stride 32) ----------------
__global__ void gather_kernel(const float* __restrict__ src, float* __restrict__ dst)
{
    int idx = blockIdx.x * blockDim.x + threadIdx.x;
    if (idx >= GM_ * D_) return;
    int d = idx & (D_ - 1);
    int t = (idx >> 9) & (GS_ - 1);
    int b = idx >> 16;
    dst[idx] = src[((size_t)(b * S_ + t * 32) << 9) + d];
}

// ---------------- linear interp 128 -> 4096 ----------------
__global__ void interp_kernel(const float* __restrict__ a, float* __restrict__ out)
{
    int idx = blockIdx.x * blockDim.x + threadIdx.x;
    if (idx >= M_ * D_) return;
    int d = idx & (D_ - 1);
    int s = (idx >> 9) & (S_ - 1);
    int b = idx >> 21;
    float pos = (s + 0.5f) * (1.0f / 32.0f) - 0.5f;
    pos = fminf(fmaxf(pos, 0.0f), (float)(GS_ - 1));
    int i0 = (int)floorf(pos);
    int i1 = min(i0 + 1, GS_ - 1);
    float w = pos - (float)i0;
    float v0 = a[((size_t)(b * GS_ + i0) << 9) + d];
    float v1 = a[((size_t)(b * GS_ + i1) << 9) + d];
    out[idx] = v0 * (1.f - w) + v1 * w;
}

// ---------------- final weighted blend + LayerNorm ----------------
__global__ void final_kernel(const float* __restrict__ xl, const float* __restrict__ xg,
                             const float* __restrict__ pfl, const float* __restrict__ pfg,
                             const float* __restrict__ g, const float* __restrict__ bb,
                             float* __restrict__ out)
{
    __shared__ float red[32];
    float fl = *pfl, fg = *pfg;
    float mx = fmaxf(fl, fg);
    float e0 = expf(fl - mx), e1 = expf(fg - mx);
    float w0 = e0 / (e0 + e1), w1 = e1 / (e0 + e1);

    size_t row = blockIdx.x;
    const float* xr = xl + row * D_;
    const float* ar = xg + row * D_;
    float v[4];
    float s = 0.f;
    #pragma unroll
    for (int i = 0; i < 4; i++) {
        int c = threadIdx.x + i * 128;
        v[i] = w0 * xr[c] + w1 * ar[c];
        s += v[i];
    }
    s = blk_reduce_sum(s, red);
    float mu = s * (1.f / D_);
    float s2 = 0.f;
    #pragma unroll
    for (int i = 0; i < 4; i++) { float d = v[i] - mu; s2 += d * d; }
    s2 = blk_reduce_sum(s2, red);
    float rstd = rsqrtf(s2 * (1.f / D_) + 1e-5f);
    #pragma unroll
    for (int i = 0; i < 4; i++) {
        int c = threadIdx.x + i * 128;
        out[row * D_ + c] = (v[i] - mu) * rstd * g[c] + bb[c];
    }
}

// ---------------- host orchestration ----------------
extern "C" void kernel_launch(void* const* d_in, const int* in_sizes, int n_in,
                              void* d_out, int out_size)
{
    const float* x       = (const float*)d_in[0];
    const float* lqkv_w  = (const float*)d_in[1];
    const float* lqkv_b  = (const float*)d_in[2];
    const float* lproj_w = (const float*)d_in[3];
    const float* lproj_b = (const float*)d_in[4];
    const float* lrel    = (const float*)d_in[5];
    const float* lconv_w = (const float*)d_in[6];
    const float* lconv_b = (const float*)d_in[7];
    const float* ln1_g   = (const float*)d_in[8];
    const float* ln1_b   = (const float*)d_in[9];
    const float* lffn_w1 = (const float*)d_in[10];
    const float* lffn_b1 = (const float*)d_in[11];
    const float* lffn_w2 = (const float*)d_in[12];
    const float* lffn_b2 = (const float*)d_in[13];
    const float* ln2_g   = (const float*)d_in[14];
    const float* ln2_b   = (const float*)d_in[15];
    const float* gqkv_w  = (const float*)d_in[16];
    const float* gqkv_b  = (const float*)d_in[17];
    const float* gproj_w = (const float*)d_in[18];
    const float* gproj_b = (const float*)d_in[19];
    const float* gn1_g   = (const float*)d_in[20];
    const float* gn1_b   = (const float*)d_in[21];
    const float* gffn_w1 = (const float*)d_in[22];
    const float* gffn_b1 = (const float*)d_in[23];
    const float* gffn_w2 = (const float*)d_in[24];
    const float* gffn_b2 = (const float*)d_in[25];
    const float* gn2_g   = (const float*)d_in[26];
    const float* gn2_b   = (const float*)d_in[27];
    const float* fw_l    = (const float*)d_in[28];
    const float* fw_g    = (const float*)d_in[29];
    const float* fn_g    = (const float*)d_in[30];
    const float* fn_b    = (const float*)d_in[31];

    float *xl, *xg, *tmp, *tmp2, *qkv, *hid, *xs, *atts, *ps;
    cudaGetSymbolAddress((void**)&xl,   g_xl);
    cudaGetSymbolAddress((void**)&xg,   g_xg);
    cudaGetSymbolAddress((void**)&tmp,  g_tmp);
    cudaGetSymbolAddress((void**)&tmp2, g_tmp2);
    cudaGetSymbolAddress((void**)&qkv,  g_qkv);
    cudaGetSymbolAddress((void**)&hid,  g_hid);
    cudaGetSymbolAddress((void**)&xs,   g_xs);
    cudaGetSymbolAddress((void**)&atts, g_atts);
    cudaGetSymbolAddress((void**)&ps,   g_ps);

    const int EW = 256;

    // ---- local branch ----
    const float* src = x;
    for (int i = 0; i < 4; i++) {
        gemm(src, lqkv_w + (size_t)i * D_ * 3 * D_, lqkv_b + (size_t)i * 3 * D_, qkv,
             M_, D_, 3 * D_, 0);
        local_attn_kernel<<<B_ * NW_ * H_, 32>>>(qkv, lrel + (size_t)i * (2 * W_ - 1) * H_, tmp);
        gemm(tmp, lproj_w + (size_t)i * D_ * D_, lproj_b + (size_t)i * D_, tmp2,
             M_, D_, D_, 0);
        add_ln_kernel<<<M_, 128>>>(src, tmp2, ln1_g + (size_t)i * D_, ln1_b + (size_t)i * D_, xl);
        dwconv_kernel<<<(M_ * D_ + EW - 1) / EW, EW>>>(xl, lconv_w + (size_t)i * D_ * 7,
                                                        lconv_b + (size_t)i * D_, tmp);
        gemm(tmp, lffn_w1 + (size_t)i * D_ * 4 * D_, lffn_b1 + (size_t)i * 4 * D_, hid,
             M_, D_, 4 * D_, 1);
        gemm(hid, lffn_w2 + (size_t)i * 4 * D_ * D_, lffn_b2 + (size_t)i * D_, tmp2,
             M_, 4 * D_, D_, 0);
        add_ln_kernel<<<M_, 128>>>(tmp, tmp2, ln2_g + (size_t)i * D_, ln2_b + (size_t)i * D_, xl);
        src = xl;
    }

    // ---- global branch ----
    const float* gsrc = x;
    for (int i = 0; i < 3; i++) {
        gather_kernel<<<(GM_ * D_ + EW - 1) / EW, EW>>>(gsrc, xs);
        gemm(xs, gqkv_w + (size_t)i * D_ * 3 * D_, gqkv_b + (size_t)i * 3 * D_, qkv,
             GM_, D_, 3 * D_, 0);
        gattn_kernel<<<B_ * H_ * GS_, 128>>>(qkv, atts);
        gemm(atts, gproj_w + (size_t)i * D_ * D_, gproj_b + (size_t)i * D_, ps,
             GM_, D_, D_, 0);
        interp_kernel<<<(M_ * D_ + EW - 1) / EW, EW>>>(ps, tmp);
        add_ln_kernel<<<M_, 128>>>(gsrc, tmp, gn1_g + (size_t)i * D_, gn1_b + (size_t)i * D_, xg);
        gemm(xg, gffn_w1 + (size_t)i * D_ * 4 * D_, gffn_b1 + (size_t)i * 4 * D_, hid,
             M_, D_, 4 * D_, 1);
        gemm(hid, gffn_w2 + (size_t)i * 4 * D_ * D_, gffn_b2 + (size_t)i * D_, tmp2,
             M_, 4 * D_, D_, 0);
        add_ln_kernel<<<M_, 128>>>(xg, tmp2, gn2_g + (size_t)i * D_, gn2_b + (size_t)i * D_, xg);
        gsrc = xg;
    }

    // ---- final blend + LN ----
    final_kernel<<<M_, 128>>>(xl, xg, fw_l, fw_g, fn_g, fn_b, (float*)d_out);
}

// round 3
// speedup vs baseline: 3.0388x; 3.0388x over previous
#include <cuda_runtime.h>
#include <math.h>
#include <stdint.h>

// ---------------- problem constants ----------------
#define B_   4
#define S_   4096
#define D_   512
#define H_   8
#define W_   32
#define HD_  64
#define NW_  (S_ / W_)        // 128
#define M_   (B_ * S_)        // 16384
#define GS_  128              // global strided seq len
#define GM_  (B_ * GS_)       // 512

// ---------------- scratch (no allocations allowed) ----------------
__device__ float g_xl  [M_ * D_];
__device__ float g_xg  [M_ * D_];
__device__ float g_xr  [M_ * D_];
__device__ float g_tmp [M_ * D_];
__device__ float g_tmp2[M_ * D_];
__device__ float g_qkv [M_ * 3 * D_];
__device__ float g_hid [M_ * 4 * D_];
__device__ float g_xs  [GM_ * D_];
__device__ float g_atts[GM_ * D_];
__device__ float g_ps  [GM_ * D_];

// transposed (and tf32-rounded) weights: W[K,N] -> WT[N,K]
__device__ float g_lqkvT [4 * 1536 * 512];
__device__ float g_lprojT[4 * 512 * 512];
__device__ float g_lffn1T[4 * 2048 * 512];
__device__ float g_lffn2T[4 * 512 * 2048];
__device__ float g_gqkvT [3 * 1536 * 512];
__device__ float g_gprojT[3 * 512 * 512];
__device__ float g_gffn1T[3 * 2048 * 512];
__device__ float g_gffn2T[3 * 512 * 2048];

// ---------------- PTX helpers (all portable: sm_80+ PTX, no sm_103a-only ops) ----------------
__device__ __forceinline__ uint32_t smem_u32(const void* p) {
    uint32_t a;
    asm("{ .reg .u64 t; cvta.to.shared.u64 t, %1; cvt.u32.u64 %0, t; }" : "=r"(a) : "l"(p));
    return a;
}

__device__ __forceinline__ float tf32r(float x) {
    uint32_t u;
    asm("cvt.rna.tf32.f32 %0, %1;" : "=r"(u) : "f"(x));
    return __uint_as_float(u);
}

#define CP_ASYNC16(dst, src) \
    asm volatile("cp.async.cg.shared.global [%0], [%1], 16;" :: "r"(dst), "l"(src))
#define CP_COMMIT() asm volatile("cp.async.commit_group;" ::: "memory")
#define CP_WAIT1()  asm volatile("cp.async.wait_group 1;" ::: "memory")

__device__ __forceinline__ void ldsm4(uint32_t& r0, uint32_t& r1, uint32_t& r2, uint32_t& r3,
                                      uint32_t addr) {
    asm volatile("ldmatrix.sync.aligned.m8n8.x4.shared.b16 {%0,%1,%2,%3}, [%4];"
                 : "=r"(r0), "=r"(r1), "=r"(r2), "=r"(r3) : "r"(addr));
}

__device__ __forceinline__ void mma8(float* c,
                                     uint32_t a0, uint32_t a1, uint32_t a2, uint32_t a3,
                                     uint32_t b0, uint32_t b1) {
    asm volatile(
        "mma.sync.aligned.m16n8k8.row.col.f32.tf32.tf32.f32 "
        "{%0,%1,%2,%3}, {%4,%5,%6,%7}, {%8,%9}, {%0,%1,%2,%3};"
        : "+f"(c[0]), "+f"(c[1]), "+f"(c[2]), "+f"(c[3])
        : "r"(a0), "r"(a1), "r"(a2), "r"(a3), "r"(b0), "r"(b1));
}

// ---------------- misc math ----------------
__device__ __forceinline__ float gelu_tanh(float x) {
    float x3 = x * x * x;
    return 0.5f * x * (1.f + tanhf(0.7978845608028654f * (x + 0.044715f * x3)));
}

__device__ __forceinline__ float blk_reduce_sum(float v, float* red) {
    int lane = threadIdx.x & 31, w = threadIdx.x >> 5;
    #pragma unroll
    for (int o = 16; o; o >>= 1) v += __shfl_xor_sync(0xffffffffu, v, o);
    if (lane == 0) red[w] = v;
    __syncthreads();
    int nw = blockDim.x >> 5;
    if (w == 0) {
        float t = (lane < nw) ? red[lane] : 0.f;
        #pragma unroll
        for (int o = 16; o; o >>= 1) t += __shfl_xor_sync(0xffffffffu, t, o);
        if (lane == 0) red[0] = t;
    }
    __syncthreads();
    float r = red[0];
    __syncthreads();
    return r;
}

__device__ __forceinline__ float blk_reduce_max(float v, float* red) {
    int lane = threadIdx.x & 31, w = threadIdx.x >> 5;
    #pragma unroll
    for (int o = 16; o; o >>= 1) v = fmaxf(v, __shfl_xor_sync(0xffffffffu, v, o));
    if (lane == 0) red[w] = v;
    __syncthreads();
    int nw = blockDim.x >> 5;
    if (w == 0) {
        float t = (lane < nw) ? red[lane] : -1e30f;
        #pragma unroll
        for (int o = 16; o; o >>= 1) t = fmaxf(t, __shfl_xor_sync(0xffffffffu, t, o));
        if (lane == 0) red[0] = t;
    }
    __syncthreads();
    float r = red[0];
    __syncthreads();
    return r;
}

// ---------------- weight transpose W[K,N] -> WT[N,K], tf32-rounded ----------------
__global__ void transpose_kernel(const float* __restrict__ src, float* __restrict__ dst,
                                 int K, int N) {
    __shared__ float t[32][33];
    int n0 = blockIdx.x * 32, k0 = blockIdx.y * 32;
    int tx = threadIdx.x, ty = threadIdx.y;   // 32 x 8
    #pragma unroll
    for (int i = 0; i < 32; i += 8)
        t[ty + i][tx] = src[(size_t)(k0 + ty + i) * N + n0 + tx];
    __syncthreads();
    #pragma unroll
    for (int i = 0; i < 32; i += 8)
        dst[(size_t)(n0 + ty + i) * K + k0 + tx] = tf32r(t[tx][ty + i]);
}

// ---------------- tf32 rounding pass ----------------
__global__ void round_kernel(const float* __restrict__ src, float* __restrict__ dst, int n) {
    int i = blockIdx.x * blockDim.x + threadIdx.x;
    if (i < n) dst[i] = tf32r(src[i]);
}

// ---------------- tf32 mma.sync GEMM ----------------
// C[M,N] = act(A[M,K] @ W[K,N] + bias), BT = W^T [N,K] row-major (tf32-rounded).
// CTA tile 128x256, BK=32, 3-stage cp.async pipeline, 8 warps each 64x64.
#define GSTAGES 3
#define STAGE_BYTES 49152            // A 16KB + B 32KB
#define GSMEM_BYTES (GSTAGES * STAGE_BYTES)

__global__ void __launch_bounds__(256, 1)
gemm_tf32_kernel(const float* __restrict__ A, const float* __restrict__ BT,
                 const float* __restrict__ bias, float* __restrict__ C,
                 int M, int K, int N, int act)
{
    extern __shared__ char smem[];
    const uint32_t sb = smem_u32(smem);
    const int tid = threadIdx.x;
    const int bm = blockIdx.y * 128;
    const int bn = blockIdx.x * 256;
    const int KT = K >> 5;

    // per-thread cp.async mapping (A: 4 chunks of 16B, B: 8 chunks)
    int a_row[4], a_dst[4];
    int b_row[8], b_dst[8];
    #pragma unroll
    for (int i = 0; i < 4; i++) {
        int id = tid + i * 256;
        int row = id >> 3, ch = id & 7;
        a_row[i] = row;
        a_dst[i] = row * 128 + ((ch ^ (row & 7)) << 4);
    }
    #pragma unroll
    for (int i = 0; i < 8; i++) {
        int id = tid + i * 256;
        int row = id >> 3, ch = id & 7;
        b_row[i] = row;
        b_dst[i] = 16384 + row * 128 + ((ch ^ (row & 7)) << 4);
    }

    float acc[4][8][4];
    #pragma unroll
    for (int mt = 0; mt < 4; mt++)
        #pragma unroll
        for (int nt = 0; nt < 8; nt++)
            #pragma unroll
            for (int q = 0; q < 4; q++) acc[mt][nt][q] = 0.f;

    const int wid = tid >> 5, lane = tid & 31;
    const int wm = (wid & 1) * 64;
    const int wn = (wid >> 1) * 64;
    const int j = lane >> 3, r = lane & 7;   // ldmatrix lane role
    const int jhi = (j & 2) ? 8 : 0;
    const int jlo = j & 1;

    // prologue: fill STAGES-1 stages
    #pragma unroll
    for (int s = 0; s < GSTAGES - 1; s++) {
        uint32_t base = sb + s * STAGE_BYTES;
        int k0 = s * 32;
        #pragma unroll
        for (int i = 0; i < 4; i++) {
            int id = tid + i * 256, ch = id & 7;
            CP_ASYNC16(base + a_dst[i], A + (size_t)(bm + a_row[i]) * K + k0 + ch * 4);
        }
        #pragma unroll
        for (int i = 0; i < 8; i++) {
            int id = tid + i * 256, ch = id & 7;
            CP_ASYNC16(base + b_dst[i], BT + (size_t)(bn + b_row[i]) * K + k0 + ch * 4);
        }
        CP_COMMIT();
    }

    for (int kt = 0; kt < KT; kt++) {
        CP_WAIT1();
        __syncthreads();

        // issue next stage
        if (kt + GSTAGES - 1 < KT) {
            int ns = (kt + GSTAGES - 1) % GSTAGES;
            uint32_t base = sb + ns * STAGE_BYTES;
            int k0 = (kt + GSTAGES - 1) * 32;
            #pragma unroll
            for (int i = 0; i < 4; i++) {
                int id = tid + i * 256, ch = id & 7;
                CP_ASYNC16(base + a_dst[i], A + (size_t)(bm + a_row[i]) * K + k0 + ch * 4);
            }
            #pragma unroll
            for (int i = 0; i < 8; i++) {
                int id = tid + i * 256, ch = id & 7;
                CP_ASYNC16(base + b_dst[i], BT + (size_t)(bn + b_row[i]) * K + k0 + ch * 4);
            }
        }
        CP_COMMIT();

        uint32_t base = sb + (kt % GSTAGES) * STAGE_BYTES;
        #pragma unroll
        for (int ks = 0; ks < 4; ks++) {
            uint32_t am0[4], am1[4], am2[4], am3[4];
            #pragma unroll
            for (int mt = 0; mt < 4; mt++) {
                int row = wm + mt * 16 + jhi + r;
                int ch = 2 * ks + jlo;
                uint32_t addr = base + row * 128 + ((ch ^ (row & 7)) << 4);
                ldsm4(am0[mt], am1[mt], am2[mt], am3[mt], addr);
            }
            uint32_t b0[8], b1[8];
            #pragma unroll
            for (int p = 0; p < 4; p++) {
                int row = wn + p * 16 + jhi + r;
                int ch = 2 * ks + jlo;
                uint32_t addr = base + 16384 + row * 128 + ((ch ^ (row & 7)) << 4);
                uint32_t t0, t1, t2, t3;
                ldsm4(t0, t1, t2, t3, addr);
                b0[2 * p] = t0; b1[2 * p] = t1;
                b0[2 * p + 1] = t2; b1[2 * p + 1] = t3;
            }
            #pragma unroll
            for (int mt = 0; mt < 4; mt++)
                #pragma unroll
                for (int nt = 0; nt < 8; nt++)
                    mma8(acc[mt][nt], am0[mt], am2[mt], am1[mt], am3[mt], b0[nt], b1[nt]);
        }
    }

    // ---- epilogue ----
    const int g = lane >> 2, c = lane & 3;
    #pragma unroll
    for (int mt = 0; mt < 4; mt++) {
        int row0 = bm + wm + mt * 16 + g;
        #pragma unroll
        for (int nt = 0; nt < 8; nt++) {
            int col0 = bn + wn + nt * 8 + 2 * c;
            float bi0 = bias[col0], bi1 = bias[col0 + 1];
            float v0 = acc[mt][nt][0] + bi0;
            float v1 = acc[mt][nt][1] + bi1;
            float v2 = acc[mt][nt][2] + bi0;
            float v3 = acc[mt][nt][3] + bi1;
            if (act == 1) {
                v0 = tf32r(gelu_tanh(v0));
                v1 = tf32r(gelu_tanh(v1));
                v2 = tf32r(gelu_tanh(v2));
                v3 = tf32r(gelu_tanh(v3));
            }
            *(float2*)&C[(size_t)row0 * N + col0]       = make_float2(v0, v1);
            *(float2*)&C[(size_t)(row0 + 8) * N + col0] = make_float2(v2, v3);
        }
    }
}

static inline void gemm_tc(const float* A, const float* BT, const float* bias, float* C,
                           int M, int K, int N, int act) {
    dim3 grid(N / 256, M / 128);
    gemm_tf32_kernel<<<grid, 256, GSMEM_BYTES>>>(A, BT, bias, C, M, K, N, act);
}

// ---------------- local windowed attention (rounds output: feeds proj GEMM) ----------------
__global__ void local_attn_kernel(const float* __restrict__ qkv,
                                  const float* __restrict__ rel,
                                  float* __restrict__ out)
{
    int blk = blockIdx.x;
    int h   = blk & (H_ - 1);
    int win = (blk >> 3) & (NW_ - 1);
    int b   = blk >> 10;
    int s0  = win * W_;
    int tid = threadIdx.x;

    __shared__ float ks[W_][HD_];
    __shared__ float vs[W_][HD_];

    size_t base = ((size_t)(b * S_ + s0)) * 1536 + h * HD_;
    for (int idx = tid; idx < W_ * HD_; idx += 32) {
        int jj = idx >> 6, d = idx & 63;
        ks[jj][d] = qkv[base + (size_t)jj * 1536 + 512 + d];
        vs[jj][d] = qkv[base + (size_t)jj * 1536 + 1024 + d];
    }
    __syncthreads();

    float q[HD_];
    {
        const float* qr = qkv + base + (size_t)tid * 1536;
        #pragma unroll
        for (int d = 0; d < HD_; d++) q[d] = qr[d];
    }

    float sc[W_];
    float m = -1e30f;
    #pragma unroll
    for (int jj = 0; jj < W_; jj++) {
        float a = 0.f;
        const float4* kj = (const float4*)ks[jj];
        #pragma unroll
        for (int d4 = 0; d4 < HD_ / 4; d4++) {
            float4 kk = kj[d4];
            a += q[4 * d4 + 0] * kk.x + q[4 * d4 + 1] * kk.y
               + q[4 * d4 + 2] * kk.z + q[4 * d4 + 3] * kk.w;
        }
        a = a * 0.125f + rel[(tid - jj + W_ - 1) * H_ + h];
        sc[jj] = a;
        m = fmaxf(m, a);
    }
    float sum = 0.f;
    #pragma unroll
    for (int jj = 0; jj < W_; jj++) { sc[jj] = expf(sc[jj] - m); sum += sc[jj]; }
    float inv = 1.f / sum;

    float o[HD_];
    #pragma unroll
    for (int d = 0; d < HD_; d++) o[d] = 0.f;
    #pragma unroll
    for (int jj = 0; jj < W_; jj++) {
        float p = sc[jj];
        const float4* vj = (const float4*)vs[jj];
        #pragma unroll
        for (int d4 = 0; d4 < HD_ / 4; d4++) {
            float4 vv = vj[d4];
            o[4 * d4 + 0] += p * vv.x;
            o[4 * d4 + 1] += p * vv.y;
            o[4 * d4 + 2] += p * vv.z;
            o[4 * d4 + 3] += p * vv.w;
        }
    }
    float* orow = out + (size_t)(b * S_ + s0 + tid) * D_ + h * HD_;
    #pragma unroll
    for (int d = 0; d < HD_; d++) orow[d] = tf32r(o[d] * inv);
}

// ---------------- global attention (rounds output: feeds proj GEMM) ----------------
__global__ void gattn_kernel(const float* __restrict__ qkv, float* __restrict__ out)
{
    int blk = blockIdx.x;
    int i = blk & (GS_ - 1);
    int h = (blk >> 7) & (H_ - 1);
    int b = blk >> 10;
    int tid = threadIdx.x;

    __shared__ float q[HD_];
    __shared__ float p[GS_];
    __shared__ float red[32];

    if (tid < HD_) q[tid] = qkv[(size_t)(b * GS_ + i) * 1536 + h * HD_ + tid];
    __syncthreads();

    float s;
    {
        const float* krow = qkv + (size_t)(b * GS_ + tid) * 1536 + 512 + h * HD_;
        float a = 0.f;
        #pragma unroll
        for (int d = 0; d < HD_; d++) a += q[d] * krow[d];
        s = a * 0.125f;
    }
    float m = blk_reduce_max(s, red);
    float e = expf(s - m);
    float sum = blk_reduce_sum(e, red);
    p[tid] = e;
    __syncthreads();

    if (tid < HD_) {
        float a = 0.f;
        for (int jj = 0; jj < GS_; jj++)
            a += p[jj] * qkv[(size_t)(b * GS_ + jj) * 1536 + 1024 + h * HD_ + tid];
        out[(size_t)(b * GS_ + i) * D_ + h * HD_ + tid] = tf32r(a / sum);
    }
}

// ---------------- fused residual add + LayerNorm (optional tf32 rounding) ----------------
__global__ void add_ln_kernel(const float* __restrict__ x, const float* __restrict__ a,
                              const float* __restrict__ g, const float* __restrict__ bb,
                              float* __restrict__ out, int round_out)
{
    __shared__ float red[32];
    size_t row = blockIdx.x;
    const float* xr = x + row * D_;
    const float* ar = a + row * D_;
    float v[4];
    float s = 0.f;
    #pragma unroll
    for (int i = 0; i < 4; i++) {
        int c = threadIdx.x + i * 128;
        v[i] = xr[c] + ar[c];
        s += v[i];
    }
    s = blk_reduce_sum(s, red);
    float mu = s * (1.f / D_);
    float s2 = 0.f;
    #pragma unroll
    for (int i = 0; i < 4; i++) { float d = v[i] - mu; s2 += d * d; }
    s2 = blk_reduce_sum(s2, red);
    float rstd = rsqrtf(s2 * (1.f / D_) + 1e-5f);
    #pragma unroll
    for (int i = 0; i < 4; i++) {
        int c = threadIdx.x + i * 128;
        float o = (v[i] - mu) * rstd * g[c] + bb[c];
        out[row * D_ + c] = round_out ? tf32r(o) : o;
    }
}

// ---------------- depthwise conv (K=7) + residual (rounds: feeds ffn1 GEMM) ----------------
__global__ void dwconv_kernel(const float* __restrict__ x, const float* __restrict__ w,
                              const float* __restrict__ cb, float* __restrict__ y)
{
    int idx = blockIdx.x * blockDim.x + threadIdx.x;
    if (idx >= M_ * D_) return;
    int d = idx & (D_ - 1);
    int s = (idx >> 9) & (S_ - 1);
    int b = idx >> 21;
    float acc = x[idx] + cb[d];
    #pragma unroll
    for (int k = 0; k < 7; k++) {
        int ss = s + k - 3;
        if (ss >= 0 && ss < S_)
            acc += w[d * 7 + k] * x[((size_t)(b * S_ + ss) << 9) + d];
    }
    y[idx] = tf32r(acc);
}

// ---------------- strided gather (stride 32), rounds (feeds qkv GEMM) ----------------
__global__ void gather_kernel(const float* __restrict__ src, float* __restrict__ dst)
{
    int idx = blockIdx.x * blockDim.x + threadIdx.x;
    if (idx >= GM_ * D_) return;
    int d = idx & (D_ - 1);
    int t = (idx >> 9) & (GS_ - 1);
    int b = idx >> 16;
    dst[idx] = tf32r(src[((size_t)(b * S_ + t * 32) << 9) + d]);
}

// ---------------- linear interp 128 -> 4096 ----------------
__global__ void interp_kernel(const float* __restrict__ a, float* __restrict__ out)
{
    int idx = blockIdx.x * blockDim.x + threadIdx.x;
    if (idx >= M_ * D_) return;
    int d = idx & (D_ - 1);
    int s = (idx >> 9) & (S_ - 1);
    int b = idx >> 21;
    float pos = (s + 0.5f) * (1.0f / 32.0f) - 0.5f;
    pos = fminf(fmaxf(pos, 0.0f), (float)(GS_ - 1));
    int i0 = (int)floorf(pos);
    int i1 = min(i0 + 1, GS_ - 1);
    float w = pos - (float)i0;
    float v0 = a[((size_t)(b * GS_ + i0) << 9) + d];
    float v1 = a[((size_t)(b * GS_ + i1) << 9) + d];
    out[idx] = v0 * (1.f - w) + v1 * w;
}

// ---------------- final weighted blend + LayerNorm ----------------
__global__ void final_kernel(const float* __restrict__ xl, const float* __restrict__ xg,
                             const float* __restrict__ pfl, const float* __restrict__ pfg,
                             const float* __restrict__ g, const float* __restrict__ bb,
                             float* __restrict__ out)
{
    __shared__ float red[32];
    float fl = *pfl, fg = *pfg;
    float mx = fmaxf(fl, fg);
    float e0 = expf(fl - mx), e1 = expf(fg - mx);
    float w0 = e0 / (e0 + e1), w1 = e1 / (e0 + e1);

    size_t row = blockIdx.x;
    const float* xr = xl + row * D_;
    const float* ar = xg + row * D_;
    float v[4];
    float s = 0.f;
    #pragma unroll
    for (int i = 0; i < 4; i++) {
        int c = threadIdx.x + i * 128;
        v[i] = w0 * xr[c] + w1 * ar[c];
        s += v[i];
    }
    s = blk_reduce_sum(s, red);
    float mu = s * (1.f / D_);
    float s2 = 0.f;
    #pragma unroll
    for (int i = 0; i < 4; i++) { float d = v[i] - mu; s2 += d * d; }
    s2 = blk_reduce_sum(s2, red);
    float rstd = rsqrtf(s2 * (1.f / D_) + 1e-5f);
    #pragma unroll
    for (int i = 0; i < 4; i++) {
        int c = threadIdx.x + i * 128;
        out[row * D_ + c] = (v[i] - mu) * rstd * g[c] + bb[c];
    }
}

// ---------------- host orchestration ----------------
static inline void transpose(const float* src, float* dst, int K, int N) {
    dim3 grid(N / 32, K / 32), blk(32, 8);
    transpose_kernel<<<grid, blk>>>(src, dst, K, N);
}

extern "C" void kernel_launch(void* const* d_in, const int* in_sizes, int n_in,
                              void* d_out, int out_size)
{
    const float* x       = (const float*)d_in[0];
    const float* lqkv_w  = (const float*)d_in[1];
    const float* lqkv_b  = (const float*)d_in[2];
    const float* lproj_w = (const float*)d_in[3];
    const float* lproj_b = (const float*)d_in[4];
    const float* lrel    = (const float*)d_in[5];
    const float* lconv_w = (const float*)d_in[6];
    const float* lconv_b = (const float*)d_in[7];
    const float* ln1_g   = (const float*)d_in[8];
    const float* ln1_b   = (const float*)d_in[9];
    const float* lffn_w1 = (const float*)d_in[10];
    const float* lffn_b1 = (const float*)d_in[11];
    const float* lffn_w2 = (const float*)d_in[12];
    const float* lffn_b2 = (const float*)d_in[13];
    const float* ln2_g   = (const float*)d_in[14];
    const float* ln2_b   = (const float*)d_in[15];
    const float* gqkv_w  = (const float*)d_in[16];
    const float* gqkv_b  = (const float*)d_in[17];
    const float* gproj_w = (const float*)d_in[18];
    const float* gproj_b = (const float*)d_in[19];
    const float* gn1_g   = (const float*)d_in[20];
    const float* gn1_b   = (const float*)d_in[21];
    const float* gffn_w1 = (const float*)d_in[22];
    const float* gffn_b1 = (const float*)d_in[23];
    const float* gffn_w2 = (const float*)d_in[24];
    const float* gffn_b2 = (const float*)d_in[25];
    const float* gn2_g   = (const float*)d_in[26];
    const float* gn2_b   = (const float*)d_in[27];
    const float* fw_l    = (const float*)d_in[28];
    const float* fw_g    = (const float*)d_in[29];
    const float* fn_g    = (const float*)d_in[30];
    const float* fn_b    = (const float*)d_in[31];

    float *xl, *xg, *xr, *tmp, *tmp2, *qkv, *hid, *xs, *atts, *ps;
    float *lqkvT, *lprojT, *lffn1T, *lffn2T, *gqkvT, *gprojT, *gffn1T, *gffn2T;
    cudaGetSymbolAddress((void**)&xl,   g_xl);
    cudaGetSymbolAddress((void**)&xg,   g_xg);
    cudaGetSymbolAddress((void**)&xr,   g_xr);
    cudaGetSymbolAddress((void**)&tmp,  g_tmp);
    cudaGetSymbolAddress((void**)&tmp2, g_tmp2);
    cudaGetSymbolAddress((void**)&qkv,  g_qkv);
    cudaGetSymbolAddress((void**)&hid,  g_hid);
    cudaGetSymbolAddress((void**)&xs,   g_xs);
    cudaGetSymbolAddress((void**)&atts, g_atts);
    cudaGetSymbolAddress((void**)&ps,   g_ps);
    cudaGetSymbolAddress((void**)&lqkvT,  g_lqkvT);
    cudaGetSymbolAddress((void**)&lprojT, g_lprojT);
    cudaGetSymbolAddress((void**)&lffn1T, g_lffn1T);
    cudaGetSymbolAddress((void**)&lffn2T, g_lffn2T);
    cudaGetSymbolAddress((void**)&gqkvT,  g_gqkvT);
    cudaGetSymbolAddress((void**)&gprojT, g_gprojT);
    cudaGetSymbolAddress((void**)&gffn1T, g_gffn1T);
    cudaGetSymbolAddress((void**)&gffn2T, g_gffn2T);

    cudaFuncSetAttribute(gemm_tf32_kernel,
                         cudaFuncAttributeMaxDynamicSharedMemorySize, GSMEM_BYTES);

    const int EW = 256;

    // ---- pre-transpose + round all weights; round x ----
    for (int i = 0; i < 4; i++) {
        transpose(lqkv_w  + (size_t)i * 512 * 1536, lqkvT  + (size_t)i * 1536 * 512, 512, 1536);
        transpose(lproj_w + (size_t)i * 512 * 512,  lprojT + (size_t)i * 512 * 512,  512, 512);
        transpose(lffn_w1 + (size_t)i * 512 * 2048, lffn1T + (size_t)i * 2048 * 512, 512, 2048);
        transpose(lffn_w2 + (size_t)i * 2048 * 512, lffn2T + (size_t)i * 512 * 2048, 2048, 512);
    }
    for (int i = 0; i < 3; i++) {
        transpose(gqkv_w  + (size_t)i * 512 * 1536, gqkvT  + (size_t)i * 1536 * 512, 512, 1536);
        transpose(gproj_w + (size_t)i * 512 * 512,  gprojT + (size_t)i * 512 * 512,  512, 512);
        transpose(gffn_w1 + (size_t)i * 512 * 2048, gffn1T + (size_t)i * 2048 * 512, 512, 2048);
        transpose(gffn_w2 + (size_t)i * 2048 * 512, gffn2T + (size_t)i * 512 * 2048, 2048, 512);
    }
    round_kernel<<<(M_ * D_ + EW - 1) / EW, EW>>>(x, xr, M_ * D_);

    // ---- local branch ----
    const float* asrc = xr;   // tf32-rounded GEMM A input
    const float* rsrc = x;    // exact residual input
    for (int i = 0; i < 4; i++) {
        gemm_tc(asrc, lqkvT + (size_t)i * 1536 * 512, lqkv_b + (size_t)i * 1536, qkv,
                M_, 512, 1536, 0);
        local_attn_kernel<<<B_ * NW_ * H_, 32>>>(qkv, lrel + (size_t)i * (2 * W_ - 1) * H_, tmp);
        gemm_tc(tmp, lprojT + (size_t)i * 512 * 512, lproj_b + (size_t)i * 512, tmp2,
                M_, 512, 512, 0);
        add_ln_kernel<<<M_, 128>>>(rsrc, tmp2, ln1_g + (size_t)i * D_, ln1_b + (size_t)i * D_,
                                   xl, 0);
        dwconv_kernel<<<(M_ * D_ + EW - 1) / EW, EW>>>(xl, lconv_w + (size_t)i * D_ * 7,
                                                        lconv_b + (size_t)i * D_, tmp);
        gemm_tc(tmp, lffn1T + (size_t)i * 2048 * 512, lffn_b1 + (size_t)i * 2048, hid,
                M_, 512, 2048, 1);
        gemm_tc(hid, lffn2T + (size_t)i * 512 * 2048, lffn_b2 + (size_t)i * 512, tmp2,
                M_, 2048, 512, 0);
        add_ln_kernel<<<M_, 128>>>(tmp, tmp2, ln2_g + (size_t)i * D_, ln2_b + (size_t)i * D_,
                                   xl, (i < 3) ? 1 : 0);
        asrc = xl;
        rsrc = xl;
    }

    // ---- global branch ----
    const float* gsrc = x;
    for (int i = 0; i < 3; i++) {
        gather_kernel<<<(GM_ * D_ + EW - 1) / EW, EW>>>(gsrc, xs);
        gemm_tc(xs, gqkvT + (size_t)i * 1536 * 512, gqkv_b + (size_t)i * 1536, qkv,
                GM_, 512, 1536, 0);
        gattn_kernel<<<B_ * H_ * GS_, 128>>>(qkv, atts);
        gemm_tc(atts, gprojT + (size_t)i * 512 * 512, gproj_b + (size_t)i * 512, ps,
                GM_, 512, 512, 0);
        interp_kernel<<<(M_ * D_ + EW - 1) / EW, EW>>>(ps, tmp);
        add_ln_kernel<<<M_, 128>>>(gsrc, tmp, gn1_g + (size_t)i * D_, gn1_b + (size_t)i * D_,
                                   xg, 1);
        gemm_tc(xg, gffn1T + (size_t)i * 2048 * 512, gffn_b1 + (size_t)i * 2048, hid,
                M_, 512, 2048, 1);
        gemm_tc(hid, gffn2T + (size_t)i * 512 * 2048, gffn_b2 + (size_t)i * 512, tmp2,
                M_, 2048, 512, 0);
        add_ln_kernel<<<M_, 128>>>(xg, tmp2, gn2_g + (size_t)i * D_, gn2_b + (size_t)i * D_,
                                   xg, 0);
        gsrc = xg;
    }

    // ---- final blend + LN ----
    final_kernel<<<M_, 128>>>(xl, xg, fw_l, fw_g, fn_g, fn_b, (float*)d_out);
}

// round 4
// speedup vs baseline: 3.3085x; 1.0888x over previous
#include <cuda_runtime.h>
#include <math.h>
#include <stdint.h>

// ---------------- problem constants ----------------
#define B_   4
#define S_   4096
#define D_   512
#define H_   8
#define W_   32
#define HD_  64
#define NW_  (S_ / W_)        // 128
#define M_   (B_ * S_)        // 16384
#define GS_  128              // global strided seq len
#define GM_  (B_ * GS_)       // 512

// ---------------- scratch (no allocations allowed) ----------------
__device__ float g_xl  [M_ * D_];
__device__ float g_xg  [M_ * D_];
__device__ float g_xr  [M_ * D_];
__device__ float g_tmp [M_ * D_];
__device__ float g_tmp2[M_ * D_];
__device__ float g_qkv [M_ * 3 * D_];
__device__ float g_hid [M_ * 4 * D_];
__device__ float g_xs  [GM_ * D_];
__device__ float g_atts[GM_ * D_];
__device__ float g_ps  [GM_ * D_];

// transposed (and tf32-rounded) weights: W[K,N] -> WT[N,K]
__device__ float g_lqkvT [4 * 1536 * 512];
__device__ float g_lprojT[4 * 512 * 512];
__device__ float g_lffn1T[4 * 2048 * 512];
__device__ float g_lffn2T[4 * 512 * 2048];
__device__ float g_gqkvT [3 * 1536 * 512];
__device__ float g_gprojT[3 * 512 * 512];
__device__ float g_gffn1T[3 * 2048 * 512];
__device__ float g_gffn2T[3 * 512 * 2048];

// ---------------- PTX helpers (portable sm_80+ PTX only) ----------------
__device__ __forceinline__ uint32_t smem_u32(const void* p) {
    uint32_t a;
    asm("{ .reg .u64 t; cvta.to.shared.u64 t, %1; cvt.u32.u64 %0, t; }" : "=r"(a) : "l"(p));
    return a;
}

__device__ __forceinline__ float tf32r(float x) {
    uint32_t u;
    asm("cvt.rna.tf32.f32 %0, %1;" : "=r"(u) : "f"(x));
    return __uint_as_float(u);
}

#define CP_ASYNC16(dst, src) \
    asm volatile("cp.async.cg.shared.global [%0], [%1], 16;" :: "r"(dst), "l"(src))
#define CP_COMMIT() asm volatile("cp.async.commit_group;" ::: "memory")
#define CP_WAIT1()  asm volatile("cp.async.wait_group 1;" ::: "memory")

__device__ __forceinline__ void ldsm4(uint32_t& r0, uint32_t& r1, uint32_t& r2, uint32_t& r3,
                                      uint32_t addr) {
    asm volatile("ldmatrix.sync.aligned.m8n8.x4.shared.b16 {%0,%1,%2,%3}, [%4];"
                 : "=r"(r0), "=r"(r1), "=r"(r2), "=r"(r3) : "r"(addr));
}

__device__ __forceinline__ void mma8(float* c,
                                     uint32_t a0, uint32_t a1, uint32_t a2, uint32_t a3,
                                     uint32_t b0, uint32_t b1) {
    asm volatile(
        "mma.sync.aligned.m16n8k8.row.col.f32.tf32.tf32.f32 "
        "{%0,%1,%2,%3}, {%4,%5,%6,%7}, {%8,%9}, {%0,%1,%2,%3};"
        : "+f"(c[0]), "+f"(c[1]), "+f"(c[2]), "+f"(c[3])
        : "r"(a0), "r"(a1), "r"(a2), "r"(a3), "r"(b0), "r"(b1));
}

// ---------------- misc math ----------------
__device__ __forceinline__ float gelu_tanh(float x) {
    float x3 = x * x * x;
    return 0.5f * x * (1.f + tanhf(0.7978845608028654f * (x + 0.044715f * x3)));
}

__device__ __forceinline__ float blk_reduce_sum(float v, float* red) {
    int lane = threadIdx.x & 31, w = threadIdx.x >> 5;
    #pragma unroll
    for (int o = 16; o; o >>= 1) v += __shfl_xor_sync(0xffffffffu, v, o);
    if (lane == 0) red[w] = v;
    __syncthreads();
    int nw = blockDim.x >> 5;
    if (w == 0) {
        float t = (lane < nw) ? red[lane] : 0.f;
        #pragma unroll
        for (int o = 16; o; o >>= 1) t += __shfl_xor_sync(0xffffffffu, t, o);
        if (lane == 0) red[0] = t;
    }
    __syncthreads();
    float r = red[0];
    __syncthreads();
    return r;
}

__device__ __forceinline__ float blk_reduce_max(float v, float* red) {
    int lane = threadIdx.x & 31, w = threadIdx.x >> 5;
    #pragma unroll
    for (int o = 16; o; o >>= 1) v = fmaxf(v, __shfl_xor_sync(0xffffffffu, v, o));
    if (lane == 0) red[w] = v;
    __syncthreads();
    int nw = blockDim.x >> 5;
    if (w == 0) {
        float t = (lane < nw) ? red[lane] : -1e30f;
        #pragma unroll
        for (int o = 16; o; o >>= 1) t = fmaxf(t, __shfl_xor_sync(0xffffffffu, t, o));
        if (lane == 0) red[0] = t;
    }
    __syncthreads();
    float r = red[0];
    __syncthreads();
    return r;
}

// ---------------- weight transpose W[K,N] -> WT[N,K], tf32-rounded ----------------
__global__ void transpose_kernel(const float* __restrict__ src, float* __restrict__ dst,
                                 int K, int N) {
    __shared__ float t[32][33];
    int n0 = blockIdx.x * 32, k0 = blockIdx.y * 32;
    int tx = threadIdx.x, ty = threadIdx.y;   // 32 x 8
    #pragma unroll
    for (int i = 0; i < 32; i += 8)
        t[ty + i][tx] = src[(size_t)(k0 + ty + i) * N + n0 + tx];
    __syncthreads();
    #pragma unroll
    for (int i = 0; i < 32; i += 8)
        dst[(size_t)(n0 + ty + i) * K + k0 + tx] = tf32r(t[tx][ty + i]);
}

// ---------------- tf32 rounding pass ----------------
__global__ void round_kernel(const float* __restrict__ src, float* __restrict__ dst, int n) {
    int i = blockIdx.x * blockDim.x + threadIdx.x;
    if (i < n) dst[i] = tf32r(src[i]);
}

// ---------------- tf32 mma.sync GEMM ----------------
// C[M,N] = act(A[M,K] @ W[K,N] + bias), BT = W^T [N,K] row-major (tf32-rounded).
// CTA tile 128x256, BK=32, 3-stage cp.async pipeline, 512 threads / 16 warps,
// warp tile 32x64 (better latency hiding than the 8-warp variant).
#define GSTAGES 3
#define STAGE_BYTES 49152            // A 16KB + B 32KB
#define GSMEM_BYTES (GSTAGES * STAGE_BYTES)

__global__ void __launch_bounds__(512, 1)
gemm_tf32_kernel(const float* __restrict__ A, const float* __restrict__ BT,
                 const float* __restrict__ bias, float* __restrict__ C,
                 int M, int K, int N, int act)
{
    extern __shared__ char smem[];
    const uint32_t sb = smem_u32(smem);
    const int tid = threadIdx.x;
    const int bm = blockIdx.y * 128;
    const int bn = blockIdx.x * 256;
    const int KT = K >> 5;

    // per-thread cp.async mapping (A: 2 chunks of 16B, B: 4 chunks)
    int a_row[2], a_dst[2];
    int b_row[4], b_dst[4];
    #pragma unroll
    for (int i = 0; i < 2; i++) {
        int id = tid + i * 512;
        int row = id >> 3, ch = id & 7;
        a_row[i] = row;
        a_dst[i] = row * 128 + ((ch ^ (row & 7)) << 4);
    }
    #pragma unroll
    for (int i = 0; i < 4; i++) {
        int id = tid + i * 512;
        int row = id >> 3, ch = id & 7;
        b_row[i] = row;
        b_dst[i] = 16384 + row * 128 + ((ch ^ (row & 7)) << 4);
    }

    float acc[2][8][4];
    #pragma unroll
    for (int mt = 0; mt < 2; mt++)
        #pragma unroll
        for (int nt = 0; nt < 8; nt++)
            #pragma unroll
            for (int q = 0; q < 4; q++) acc[mt][nt][q] = 0.f;

    const int wid = tid >> 5, lane = tid & 31;
    const int wm = (wid & 3) * 32;
    const int wn = (wid >> 2) * 64;
    const int j = lane >> 3, r = lane & 7;   // ldmatrix lane role
    const int jhi = (j & 2) ? 8 : 0;
    const int jlo = j & 1;

    // prologue: fill STAGES-1 stages
    #pragma unroll
    for (int s = 0; s < GSTAGES - 1; s++) {
        uint32_t base = sb + s * STAGE_BYTES;
        int k0 = s * 32;
        #pragma unroll
        for (int i = 0; i < 2; i++) {
            int id = tid + i * 512, ch = id & 7;
            CP_ASYNC16(base + a_dst[i], A + (size_t)(bm + a_row[i]) * K + k0 + ch * 4);
        }
        #pragma unroll
        for (int i = 0; i < 4; i++) {
            int id = tid + i * 512, ch = id & 7;
            CP_ASYNC16(base + b_dst[i], BT + (size_t)(bn + b_row[i]) * K + k0 + ch * 4);
        }
        CP_COMMIT();
    }

    for (int kt = 0; kt < KT; kt++) {
        CP_WAIT1();
        __syncthreads();

        // issue next stage
        if (kt + GSTAGES - 1 < KT) {
            int ns = (kt + GSTAGES - 1) % GSTAGES;
            uint32_t base = sb + ns * STAGE_BYTES;
            int k0 = (kt + GSTAGES - 1) * 32;
            #pragma unroll
            for (int i = 0; i < 2; i++) {
                int id = tid + i * 512, ch = id & 7;
                CP_ASYNC16(base + a_dst[i], A + (size_t)(bm + a_row[i]) * K + k0 + ch * 4);
            }
            #pragma unroll
            for (int i = 0; i < 4; i++) {
                int id = tid + i * 512, ch = id & 7;
                CP_ASYNC16(base + b_dst[i], BT + (size_t)(bn + b_row[i]) * K + k0 + ch * 4);
            }
        }
        CP_COMMIT();

        uint32_t base = sb + (kt % GSTAGES) * STAGE_BYTES;
        #pragma unroll
        for (int ks = 0; ks < 4; ks++) {
            uint32_t am0[2], am1[2], am2[2], am3[2];
            #pragma unroll
            for (int mt = 0; mt < 2; mt++) {
                int row = wm + mt * 16 + jhi + r;
                int ch = 2 * ks + jlo;
                uint32_t addr = base + row * 128 + ((ch ^ (row & 7)) << 4);
                ldsm4(am0[mt], am1[mt], am2[mt], am3[mt], addr);
            }
            uint32_t b0[8], b1[8];
            #pragma unroll
            for (int p = 0; p < 4; p++) {
                int row = wn + p * 16 + jhi + r;
                int ch = 2 * ks + jlo;
                uint32_t addr = base + 16384 + row * 128 + ((ch ^ (row & 7)) << 4);
                uint32_t t0, t1, t2, t3;
                ldsm4(t0, t1, t2, t3, addr);
                b0[2 * p] = t0; b1[2 * p] = t1;
                b0[2 * p + 1] = t2; b1[2 * p + 1] = t3;
            }
            #pragma unroll
            for (int mt = 0; mt < 2; mt++)
                #pragma unroll
                for (int nt = 0; nt < 8; nt++)
                    mma8(acc[mt][nt], am0[mt], am2[mt], am1[mt], am3[mt], b0[nt], b1[nt]);
        }
    }

    // ---- epilogue ----
    const int g = lane >> 2, c = lane & 3;
    #pragma unroll
    for (int mt = 0; mt < 2; mt++) {
        int row0 = bm + wm + mt * 16 + g;
        #pragma unroll
        for (int nt = 0; nt < 8; nt++) {
            int col0 = bn + wn + nt * 8 + 2 * c;
            float bi0 = bias[col0], bi1 = bias[col0 + 1];
            float v0 = acc[mt][nt][0] + bi0;
            float v1 = acc[mt][nt][1] + bi1;
            float v2 = acc[mt][nt][2] + bi0;
            float v3 = acc[mt][nt][3] + bi1;
            if (act == 1) {
                v0 = tf32r(gelu_tanh(v0));
                v1 = tf32r(gelu_tanh(v1));
                v2 = tf32r(gelu_tanh(v2));
                v3 = tf32r(gelu_tanh(v3));
            }
            *(float2*)&C[(size_t)row0 * N + col0]       = make_float2(v0, v1);
            *(float2*)&C[(size_t)(row0 + 8) * N + col0] = make_float2(v2, v3);
        }
    }
}

static inline void gemm_tc(const float* A, const float* BT, const float* bias, float* C,
                           int M, int K, int N, int act) {
    dim3 grid(N / 256, M / 128);
    gemm_tf32_kernel<<<grid, 512, GSMEM_BYTES>>>(A, BT, bias, C, M, K, N, act);
}

// ---------------- local windowed attention (rounds output: feeds proj GEMM) ----------------
__global__ void local_attn_kernel(const float* __restrict__ qkv,
                                  const float* __restrict__ rel,
                                  float* __restrict__ out)
{
    int blk = blockIdx.x;
    int h   = blk & (H_ - 1);
    int win = (blk >> 3) & (NW_ - 1);
    int b   = blk >> 10;
    int s0  = win * W_;
    int tid = threadIdx.x;

    __shared__ float ks[W_][HD_];
    __shared__ float vs[W_][HD_];

    size_t base = ((size_t)(b * S_ + s0)) * 1536 + h * HD_;
    for (int idx = tid; idx < W_ * HD_; idx += 32) {
        int jj = idx >> 6, d = idx & 63;
        ks[jj][d] = qkv[base + (size_t)jj * 1536 + 512 + d];
        vs[jj][d] = qkv[base + (size_t)jj * 1536 + 1024 + d];
    }
    __syncthreads();

    float q[HD_];
    {
        const float* qr = qkv + base + (size_t)tid * 1536;
        #pragma unroll
        for (int d = 0; d < HD_; d++) q[d] = qr[d];
    }

    float sc[W_];
    float m = -1e30f;
    #pragma unroll
    for (int jj = 0; jj < W_; jj++) {
        float a = 0.f;
        const float4* kj = (const float4*)ks[jj];
        #pragma unroll
        for (int d4 = 0; d4 < HD_ / 4; d4++) {
            float4 kk = kj[d4];
            a += q[4 * d4 + 0] * kk.x + q[4 * d4 + 1] * kk.y
               + q[4 * d4 + 2] * kk.z + q[4 * d4 + 3] * kk.w;
        }
        a = a * 0.125f + rel[(tid - jj + W_ - 1) * H_ + h];
        sc[jj] = a;
        m = fmaxf(m, a);
    }
    float sum = 0.f;
    #pragma unroll
    for (int jj = 0; jj < W_; jj++) { sc[jj] = expf(sc[jj] - m); sum += sc[jj]; }
    float inv = 1.f / sum;

    float o[HD_];
    #pragma unroll
    for (int d = 0; d < HD_; d++) o[d] = 0.f;
    #pragma unroll
    for (int jj = 0; jj < W_; jj++) {
        float p = sc[jj];
        const float4* vj = (const float4*)vs[jj];
        #pragma unroll
        for (int d4 = 0; d4 < HD_ / 4; d4++) {
            float4 vv = vj[d4];
            o[4 * d4 + 0] += p * vv.x;
            o[4 * d4 + 1] += p * vv.y;
            o[4 * d4 + 2] += p * vv.z;
            o[4 * d4 + 3] += p * vv.w;
        }
    }
    float* orow = out + (size_t)(b * S_ + s0 + tid) * D_ + h * HD_;
    #pragma unroll
    for (int d = 0; d < HD_; d++) orow[d] = tf32r(o[d] * inv);
}

// ---------------- global attention (rounds output: feeds proj GEMM) ----------------
__global__ void gattn_kernel(const float* __restrict__ qkv, float* __restrict__ out)
{
    int blk = blockIdx.x;
    int i = blk & (GS_ - 1);
    int h = (blk >> 7) & (H_ - 1);
    int b = blk >> 10;
    int tid = threadIdx.x;

    __shared__ float q[HD_];
    __shared__ float p[GS_];
    __shared__ float red[32];

    if (tid < HD_) q[tid] = qkv[(size_t)(b * GS_ + i) * 1536 + h * HD_ + tid];
    __syncthreads();

    float s;
    {
        const float* krow = qkv + (size_t)(b * GS_ + tid) * 1536 + 512 + h * HD_;
        float a = 0.f;
        #pragma unroll
        for (int d = 0; d < HD_; d++) a += q[d] * krow[d];
        s = a * 0.125f;
    }
    float m = blk_reduce_max(s, red);
    float e = expf(s - m);
    float sum = blk_reduce_sum(e, red);
    p[tid] = e;
    __syncthreads();

    if (tid < HD_) {
        float a = 0.f;
        for (int jj = 0; jj < GS_; jj++)
            a += p[jj] * qkv[(size_t)(b * GS_ + jj) * 1536 + 1024 + h * HD_ + tid];
        out[(size_t)(b * GS_ + i) * D_ + h * HD_ + tid] = tf32r(a / sum);
    }
}

// ---------------- fused residual add + LayerNorm (optional tf32 rounding) ----------------
__global__ void add_ln_kernel(const float* __restrict__ x, const float* __restrict__ a,
                              const float* __restrict__ g, const float* __restrict__ bb,
                              float* __restrict__ out, int round_out)
{
    __shared__ float red[32];
    size_t row = blockIdx.x;
    const float* xr = x + row * D_;
    const float* ar = a + row * D_;
    float v[4];
    float s = 0.f;
    #pragma unroll
    for (int i = 0; i < 4; i++) {
        int c = threadIdx.x + i * 128;
        v[i] = xr[c] + ar[c];
        s += v[i];
    }
    s = blk_reduce_sum(s, red);
    float mu = s * (1.f / D_);
    float s2 = 0.f;
    #pragma unroll
    for (int i = 0; i < 4; i++) { float d = v[i] - mu; s2 += d * d; }
    s2 = blk_reduce_sum(s2, red);
    float rstd = rsqrtf(s2 * (1.f / D_) + 1e-5f);
    #pragma unroll
    for (int i = 0; i < 4; i++) {
        int c = threadIdx.x + i * 128;
        float o = (v[i] - mu) * rstd * g[c] + bb[c];
        out[row * D_ + c] = round_out ? tf32r(o) : o;
    }
}

// ---------------- depthwise conv (K=7) + residual (rounds: feeds ffn1 GEMM) ----------------
__global__ void dwconv_kernel(const float* __restrict__ x, const float* __restrict__ w,
                              const float* __restrict__ cb, float* __restrict__ y)
{
    int idx = blockIdx.x * blockDim.x + threadIdx.x;
    if (idx >= M_ * D_) return;
    int d = idx & (D_ - 1);
    int s = (idx >> 9) & (S_ - 1);
    int b = idx >> 21;
    float acc = x[idx] + cb[d];
    #pragma unroll
    for (int k = 0; k < 7; k++) {
        int ss = s + k - 3;
        if (ss >= 0 && ss < S_)
            acc += w[d * 7 + k] * x[((size_t)(b * S_ + ss) << 9) + d];
    }
    y[idx] = tf32r(acc);
}

// ---------------- strided gather (stride 32), rounds (feeds qkv GEMM) ----------------
__global__ void gather_kernel(const float* __restrict__ src, float* __restrict__ dst)
{
    int idx = blockIdx.x * blockDim.x + threadIdx.x;
    if (idx >= GM_ * D_) return;
    int d = idx & (D_ - 1);
    int t = (idx >> 9) & (GS_ - 1);
    int b = idx >> 16;
    dst[idx] = tf32r(src[((size_t)(b * S_ + t * 32) << 9) + d]);
}

// ---------------- linear interp 128 -> 4096 ----------------
__global__ void interp_kernel(const float* __restrict__ a, float* __restrict__ out)
{
    int idx = blockIdx.x * blockDim.x + threadIdx.x;
    if (idx >= M_ * D_) return;
    int d = idx & (D_ - 1);
    int s = (idx >> 9) & (S_ - 1);
    int b = idx >> 21;
    float pos = (s + 0.5f) * (1.0f / 32.0f) - 0.5f;
    pos = fminf(fmaxf(pos, 0.0f), (float)(GS_ - 1));
    int i0 = (int)floorf(pos);
    int i1 = min(i0 + 1, GS_ - 1);
    float w = pos - (float)i0;
    float v0 = a[((size_t)(b * GS_ + i0) << 9) + d];
    float v1 = a[((size_t)(b * GS_ + i1) << 9) + d];
    out[idx] = v0 * (1.f - w) + v1 * w;
}

// ---------------- final weighted blend + LayerNorm ----------------
__global__ void final_kernel(const float* __restrict__ xl, const float* __restrict__ xg,
                             const float* __restrict__ pfl, const float* __restrict__ pfg,
                             const float* __restrict__ g, const float* __restrict__ bb,
                             float* __restrict__ out)
{
    __shared__ float red[32];
    float fl = *pfl, fg = *pfg;
    float mx = fmaxf(fl, fg);
    float e0 = expf(fl - mx), e1 = expf(fg - mx);
    float w0 = e0 / (e0 + e1), w1 = e1 / (e0 + e1);

    size_t row = blockIdx.x;
    const float* xr = xl + row * D_;
    const float* ar = xg + row * D_;
    float v[4];
    float s = 0.f;
    #pragma unroll
    for (int i = 0; i < 4; i++) {
        int c = threadIdx.x + i * 128;
        v[i] = w0 * xr[c] + w1 * ar[c];
        s += v[i];
    }
    s = blk_reduce_sum(s, red);
    float mu = s * (1.f / D_);
    float s2 = 0.f;
    #pragma unroll
    for (int i = 0; i < 4; i++) { float d = v[i] - mu; s2 += d * d; }
    s2 = blk_reduce_sum(s2, red);
    float rstd = rsqrtf(s2 * (1.f / D_) + 1e-5f);
    #pragma unroll
    for (int i = 0; i < 4; i++) {
        int c = threadIdx.x + i * 128;
        out[row * D_ + c] = (v[i] - mu) * rstd * g[c] + bb[c];
    }
}

// ---------------- host orchestration ----------------
static inline void transpose(const float* src, float* dst, int K, int N) {
    dim3 grid(N / 32, K / 32), blk(32, 8);
    transpose_kernel<<<grid, blk>>>(src, dst, K, N);
}

extern "C" void kernel_launch(void* const* d_in, const int* in_sizes, int n_in,
                              void* d_out, int out_size)
{
    const float* x       = (const float*)d_in[0];
    const float* lqkv_w  = (const float*)d_in[1];
    const float* lqkv_b  = (const float*)d_in[2];
    const float* lproj_w = (const float*)d_in[3];
    const float* lproj_b = (const float*)d_in[4];
    const float* lrel    = (const float*)d_in[5];
    const float* lconv_w = (const float*)d_in[6];
    const float* lconv_b = (const float*)d_in[7];
    const float* ln1_g   = (const float*)d_in[8];
    const float* ln1_b   = (const float*)d_in[9];
    const float* lffn_w1 = (const float*)d_in[10];
    const float* lffn_b1 = (const float*)d_in[11];
    const float* lffn_w2 = (const float*)d_in[12];
    const float* lffn_b2 = (const float*)d_in[13];
    const float* ln2_g   = (const float*)d_in[14];
    const float* ln2_b   = (const float*)d_in[15];
    const float* gqkv_w  = (const float*)d_in[16];
    const float* gqkv_b  = (const float*)d_in[17];
    const float* gproj_w = (const float*)d_in[18];
    const float* gproj_b = (const float*)d_in[19];
    const float* gn1_g   = (const float*)d_in[20];
    const float* gn1_b   = (const float*)d_in[21];
    const float* gffn_w1 = (const float*)d_in[22];
    const float* gffn_b1 = (const float*)d_in[23];
    const float* gffn_w2 = (const float*)d_in[24];
    const float* gffn_b2 = (const float*)d_in[25];
    const float* gn2_g   = (const float*)d_in[26];
    const float* gn2_b   = (const float*)d_in[27];
    const float* fw_l    = (const float*)d_in[28];
    const float* fw_g    = (const float*)d_in[29];
    const float* fn_g    = (const float*)d_in[30];
    const float* fn_b    = (const float*)d_in[31];

    float *xl, *xg, *xr, *tmp, *tmp2, *qkv, *hid, *xs, *atts, *ps;
    float *lqkvT, *lprojT, *lffn1T, *lffn2T, *gqkvT, *gprojT, *gffn1T, *gffn2T;
    cudaGetSymbolAddress((void**)&xl,   g_xl);
    cudaGetSymbolAddress((void**)&xg,   g_xg);
    cudaGetSymbolAddress((void**)&xr,   g_xr);
    cudaGetSymbolAddress((void**)&tmp,  g_tmp);
    cudaGetSymbolAddress((void**)&tmp2, g_tmp2);
    cudaGetSymbolAddress((void**)&qkv,  g_qkv);
    cudaGetSymbolAddress((void**)&hid,  g_hid);
    cudaGetSymbolAddress((void**)&xs,   g_xs);
    cudaGetSymbolAddress((void**)&atts, g_atts);
    cudaGetSymbolAddress((void**)&ps,   g_ps);
    cudaGetSymbolAddress((void**)&lqkvT,  g_lqkvT);
    cudaGetSymbolAddress((void**)&lprojT, g_lprojT);
    cudaGetSymbolAddress((void**)&lffn1T, g_lffn1T);
    cudaGetSymbolAddress((void**)&lffn2T, g_lffn2T);
    cudaGetSymbolAddress((void**)&gqkvT,  g_gqkvT);
    cudaGetSymbolAddress((void**)&gprojT, g_gprojT);
    cudaGetSymbolAddress((void**)&gffn1T, g_gffn1T);
    cudaGetSymbolAddress((void**)&gffn2T, g_gffn2T);

    cudaFuncSetAttribute(gemm_tf32_kernel,
                         cudaFuncAttributeMaxDynamicSharedMemorySize, GSMEM_BYTES);

    const int EW = 256;

    // ---- launch-order: round + layer0 transposes first so launch #6 = qkv GEMM ----
    round_kernel<<<(M_ * D_ + EW - 1) / EW, EW>>>(x, xr, M_ * D_);                       // 1

    // ---- local branch ----
    const float* asrc = xr;   // tf32-rounded GEMM A input
    const float* rsrc = x;    // exact residual input
    for (int i = 0; i < 4; i++) {
        transpose(lqkv_w  + (size_t)i * 512 * 1536, lqkvT  + (size_t)i * 1536 * 512, 512, 1536);
        transpose(lproj_w + (size_t)i * 512 * 512,  lprojT + (size_t)i * 512 * 512,  512, 512);
        transpose(lffn_w1 + (size_t)i * 512 * 2048, lffn1T + (size_t)i * 2048 * 512, 512, 2048);
        transpose(lffn_w2 + (size_t)i * 2048 * 512, lffn2T + (size_t)i * 512 * 2048, 2048, 512);

        gemm_tc(asrc, lqkvT + (size_t)i * 1536 * 512, lqkv_b + (size_t)i * 1536, qkv,
                M_, 512, 1536, 0);   // launch #6 on i==0 -> ncu target
        local_attn_kernel<<<B_ * NW_ * H_, 32>>>(qkv, lrel + (size_t)i * (2 * W_ - 1) * H_, tmp);
        gemm_tc(tmp, lprojT + (size_t)i * 512 * 512, lproj_b + (size_t)i * 512, tmp2,
                M_, 512, 512, 0);
        add_ln_kernel<<<M_, 128>>>(rsrc, tmp2, ln1_g + (size_t)i * D_, ln1_b + (size_t)i * D_,
                                   xl, 0);
        dwconv_kernel<<<(M_ * D_ + EW - 1) / EW, EW>>>(xl, lconv_w + (size_t)i * D_ * 7,
                                                        lconv_b + (size_t)i * D_, tmp);
        gemm_tc(tmp, lffn1T + (size_t)i * 2048 * 512, lffn_b1 + (size_t)i * 2048, hid,
                M_, 512, 2048, 1);
        gemm_tc(hid, lffn2T + (size_t)i * 512 * 2048, lffn_b2 + (size_t)i * 512, tmp2,
                M_, 2048, 512, 0);
        add_ln_kernel<<<M_, 128>>>(tmp, tmp2, ln2_g + (size_t)i * D_, ln2_b + (size_t)i * D_,
                                   xl, (i < 3) ? 1 : 0);
        asrc = xl;
        rsrc = xl;
    }

    // ---- global branch ----
    const float* gsrc = x;
    for (int i = 0; i < 3; i++) {
        transpose(gqkv_w  + (size_t)i * 512 * 1536, gqkvT  + (size_t)i * 1536 * 512, 512, 1536);
        transpose(gproj_w + (size_t)i * 512 * 512,  gprojT + (size_t)i * 512 * 512,  512, 512);
        transpose(gffn_w1 + (size_t)i * 512 * 2048, gffn1T + (size_t)i * 2048 * 512, 512, 2048);
        transpose(gffn_w2 + (size_t)i * 2048 * 512, gffn2T + (size_t)i * 512 * 2048, 2048, 512);

        gather_kernel<<<(GM_ * D_ + EW - 1) / EW, EW>>>(gsrc, xs);
        gemm_tc(xs, gqkvT + (size_t)i * 1536 * 512, gqkv_b + (size_t)i * 1536, qkv,
                GM_, 512, 1536, 0);
        gattn_kernel<<<B_ * H_ * GS_, 128>>>(qkv, atts);
        gemm_tc(atts, gprojT + (size_t)i * 512 * 512, gproj_b + (size_t)i * 512, ps,
                GM_, 512, 512, 0);
        interp_kernel<<<(M_ * D_ + EW - 1) / EW, EW>>>(ps, tmp);
        add_ln_kernel<<<M_, 128>>>(gsrc, tmp, gn1_g + (size_t)i * D_, gn1_b + (size_t)i * D_,
                                   xg, 1);
        gemm_tc(xg, gffn1T + (size_t)i * 2048 * 512, gffn_b1 + (size_t)i * 2048, hid,
                M_, 512, 2048, 1);
        gemm_tc(hid, gffn2T + (size_t)i * 512 * 2048, gffn_b2 + (size_t)i * 512, tmp2,
                M_, 2048, 512, 0);
        add_ln_kernel<<<M_, 128>>>(xg, tmp2, gn2_g + (size_t)i * D_, gn2_b + (size_t)i * D_,
                                   xg, 0);
        gsrc = xg;
    }

    // ---- final blend + LN ----
    final_kernel<<<M_, 128>>>(xl, xg, fw_l, fw_g, fn_g, fn_b, (float*)d_out);
}

// round 5
// speedup vs baseline: 3.3741x; 1.0198x over previous
#include <cuda_runtime.h>
#include <math.h>
#include <stdint.h>

// ---------------- problem constants ----------------
#define B_   4
#define S_   4096
#define D_   512
#define H_   8
#define W_   32
#define HD_  64
#define NW_  (S_ / W_)        // 128
#define M_   (B_ * S_)        // 16384
#define GS_  128              // global strided seq len
#define GM_  (B_ * GS_)       // 512

// ---------------- scratch (no allocations allowed) ----------------
__device__ float g_xl  [M_ * D_];
__device__ float g_xg  [M_ * D_];
__device__ float g_xr  [M_ * D_];
__device__ float g_tmp [M_ * D_];
__device__ float g_tmp2[M_ * D_];
__device__ float g_qkv [M_ * 3 * D_];
__device__ float g_hid [M_ * 4 * D_];
__device__ float g_xs  [GM_ * D_];
__device__ float g_atts[GM_ * D_];
__device__ float g_ps  [GM_ * D_];

// transposed (and tf32-rounded) weights: W[K,N] -> WT[N,K]
__device__ float g_lqkvT [4 * 1536 * 512];
__device__ float g_lprojT[4 * 512 * 512];
__device__ float g_lffn1T[4 * 2048 * 512];
__device__ float g_lffn2T[4 * 512 * 2048];
__device__ float g_gqkvT [3 * 1536 * 512];
__device__ float g_gprojT[3 * 512 * 512];
__device__ float g_gffn1T[3 * 2048 * 512];
__device__ float g_gffn2T[3 * 512 * 2048];

// ---------------- PTX helpers (portable sm_80+ PTX only) ----------------
__device__ __forceinline__ uint32_t smem_u32(const void* p) {
    uint32_t a;
    asm("{ .reg .u64 t; cvta.to.shared.u64 t, %1; cvt.u32.u64 %0, t; }" : "=r"(a) : "l"(p));
    return a;
}

__device__ __forceinline__ float tf32r(float x) {
    uint32_t u;
    asm("cvt.rna.tf32.f32 %0, %1;" : "=r"(u) : "f"(x));
    return __uint_as_float(u);
}

#define CP_ASYNC16(dst, src) \
    asm volatile("cp.async.cg.shared.global [%0], [%1], 16;" :: "r"(dst), "l"(src))
#define CP_COMMIT() asm volatile("cp.async.commit_group;" ::: "memory")
#define CP_WAIT1()  asm volatile("cp.async.wait_group 1;" ::: "memory")

__device__ __forceinline__ void ldsm4(uint32_t& r0, uint32_t& r1, uint32_t& r2, uint32_t& r3,
                                      uint32_t addr) {
    asm volatile("ldmatrix.sync.aligned.m8n8.x4.shared.b16 {%0,%1,%2,%3}, [%4];"
                 : "=r"(r0), "=r"(r1), "=r"(r2), "=r"(r3) : "r"(addr));
}

__device__ __forceinline__ void mma8(float* c,
                                     uint32_t a0, uint32_t a1, uint32_t a2, uint32_t a3,
                                     uint32_t b0, uint32_t b1) {
    asm volatile(
        "mma.sync.aligned.m16n8k8.row.col.f32.tf32.tf32.f32 "
        "{%0,%1,%2,%3}, {%4,%5,%6,%7}, {%8,%9}, {%0,%1,%2,%3};"
        : "+f"(c[0]), "+f"(c[1]), "+f"(c[2]), "+f"(c[3])
        : "r"(a0), "r"(a1), "r"(a2), "r"(a3), "r"(b0), "r"(b1));
}

// ---------------- misc math ----------------
__device__ __forceinline__ float gelu_tanh(float x) {
    float x3 = x * x * x;
    return 0.5f * x * (1.f + tanhf(0.7978845608028654f * (x + 0.044715f * x3)));
}

__device__ __forceinline__ float blk_reduce_sum(float v, float* red) {
    int lane = threadIdx.x & 31, w = threadIdx.x >> 5;
    #pragma unroll
    for (int o = 16; o; o >>= 1) v += __shfl_xor_sync(0xffffffffu, v, o);
    if (lane == 0) red[w] = v;
    __syncthreads();
    int nw = blockDim.x >> 5;
    if (w == 0) {
        float t = (lane < nw) ? red[lane] : 0.f;
        #pragma unroll
        for (int o = 16; o; o >>= 1) t += __shfl_xor_sync(0xffffffffu, t, o);
        if (lane == 0) red[0] = t;
    }
    __syncthreads();
    float r = red[0];
    __syncthreads();
    return r;
}

__device__ __forceinline__ float blk_reduce_max(float v, float* red) {
    int lane = threadIdx.x & 31, w = threadIdx.x >> 5;
    #pragma unroll
    for (int o = 16; o; o >>= 1) v = fmaxf(v, __shfl_xor_sync(0xffffffffu, v, o));
    if (lane == 0) red[w] = v;
    __syncthreads();
    int nw = blockDim.x >> 5;
    if (w == 0) {
        float t = (lane < nw) ? red[lane] : -1e30f;
        #pragma unroll
        for (int o = 16; o; o >>= 1) t = fmaxf(t, __shfl_xor_sync(0xffffffffu, t, o));
        if (lane == 0) red[0] = t;
    }
    __syncthreads();
    float r = red[0];
    __syncthreads();
    return r;
}

// ---------------- weight transpose W[K,N] -> WT[N,K], tf32-rounded ----------------
__global__ void transpose_kernel(const float* __restrict__ src, float* __restrict__ dst,
                                 int K, int N) {
    __shared__ float t[32][33];
    int n0 = blockIdx.x * 32, k0 = blockIdx.y * 32;
    int tx = threadIdx.x, ty = threadIdx.y;   // 32 x 8
    #pragma unroll
    for (int i = 0; i < 32; i += 8)
        t[ty + i][tx] = src[(size_t)(k0 + ty + i) * N + n0 + tx];
    __syncthreads();
    #pragma unroll
    for (int i = 0; i < 32; i += 8)
        dst[(size_t)(n0 + ty + i) * K + k0 + tx] = tf32r(t[tx][ty + i]);
}

// ---------------- tf32 rounding pass ----------------
__global__ void round_kernel(const float* __restrict__ src, float* __restrict__ dst, int n) {
    int i = blockIdx.x * blockDim.x + threadIdx.x;
    if (i < n) dst[i] = tf32r(src[i]);
}

// ---------------- tf32 mma.sync GEMM ----------------
// C[M,N] = act(A[M,K] @ W[K,N] + bias), BT = W^T [N,K] row-major (tf32-rounded).
// CTA tile 128x128, BK=32, 3-stage cp.async pipeline, 256 threads / 8 warps,
// warp tile 32x64. 96KB smem/CTA + <=128 regs => 2 CTAs/SM to overlap
// barrier/pipeline bubbles across CTAs.
#define GSTAGES 3
#define STAGE_BYTES 32768            // A 16KB + B 16KB
#define GSMEM_BYTES (GSTAGES * STAGE_BYTES)

__global__ void __launch_bounds__(256, 2)
gemm_tf32_kernel(const float* __restrict__ A, const float* __restrict__ BT,
                 const float* __restrict__ bias, float* __restrict__ C,
                 int M, int K, int N, int act)
{
    extern __shared__ char smem[];
    const uint32_t sb = smem_u32(smem);
    const int tid = threadIdx.x;
    const int bm = blockIdx.y * 128;
    const int bn = blockIdx.x * 128;
    const int KT = K >> 5;

    // per-thread cp.async mapping (A: 4 chunks of 16B, B: 4 chunks)
    int a_row[4], a_dst[4];
    int b_row[4], b_dst[4];
    #pragma unroll
    for (int i = 0; i < 4; i++) {
        int id = tid + i * 256;
        int row = id >> 3, ch = id & 7;
        a_row[i] = row;
        a_dst[i] = row * 128 + ((ch ^ (row & 7)) << 4);
        b_row[i] = row;
        b_dst[i] = 16384 + row * 128 + ((ch ^ (row & 7)) << 4);
    }

    float acc[2][8][4];
    #pragma unroll
    for (int mt = 0; mt < 2; mt++)
        #pragma unroll
        for (int nt = 0; nt < 8; nt++)
            #pragma unroll
            for (int q = 0; q < 4; q++) acc[mt][nt][q] = 0.f;

    const int wid = tid >> 5, lane = tid & 31;
    const int wm = (wid & 3) * 32;
    const int wn = (wid >> 2) * 64;
    const int j = lane >> 3, r = lane & 7;   // ldmatrix lane role
    const int jhi = (j & 2) ? 8 : 0;
    const int jlo = j & 1;

    // prologue: fill STAGES-1 stages
    #pragma unroll
    for (int s = 0; s < GSTAGES - 1; s++) {
        uint32_t base = sb + s * STAGE_BYTES;
        int k0 = s * 32;
        #pragma unroll
        for (int i = 0; i < 4; i++) {
            int id = tid + i * 256, ch = id & 7;
            CP_ASYNC16(base + a_dst[i], A + (size_t)(bm + a_row[i]) * K + k0 + ch * 4);
            CP_ASYNC16(base + b_dst[i], BT + (size_t)(bn + b_row[i]) * K + k0 + ch * 4);
        }
        CP_COMMIT();
    }

    for (int kt = 0; kt < KT; kt++) {
        CP_WAIT1();
        __syncthreads();

        // issue next stage
        if (kt + GSTAGES - 1 < KT) {
            int ns = (kt + GSTAGES - 1) % GSTAGES;
            uint32_t base = sb + ns * STAGE_BYTES;
            int k0 = (kt + GSTAGES - 1) * 32;
            #pragma unroll
            for (int i = 0; i < 4; i++) {
                int id = tid + i * 256, ch = id & 7;
                CP_ASYNC16(base + a_dst[i], A + (size_t)(bm + a_row[i]) * K + k0 + ch * 4);
                CP_ASYNC16(base + b_dst[i], BT + (size_t)(bn + b_row[i]) * K + k0 + ch * 4);
            }
        }
        CP_COMMIT();

        uint32_t base = sb + (kt % GSTAGES) * STAGE_BYTES;
        #pragma unroll
        for (int ks = 0; ks < 4; ks++) {
            uint32_t am0[2], am1[2], am2[2], am3[2];
            #pragma unroll
            for (int mt = 0; mt < 2; mt++) {
                int row = wm + mt * 16 + jhi + r;
                int ch = 2 * ks + jlo;
                uint32_t addr = base + row * 128 + ((ch ^ (row & 7)) << 4);
                ldsm4(am0[mt], am1[mt], am2[mt], am3[mt], addr);
            }
            uint32_t b0[8], b1[8];
            #pragma unroll
            for (int p = 0; p < 4; p++) {
                int row = wn + p * 16 + jhi + r;
                int ch = 2 * ks + jlo;
                uint32_t addr = base + 16384 + row * 128 + ((ch ^ (row & 7)) << 4);
                uint32_t t0, t1, t2, t3;
                ldsm4(t0, t1, t2, t3, addr);
                b0[2 * p] = t0; b1[2 * p] = t1;
                b0[2 * p + 1] = t2; b1[2 * p + 1] = t3;
            }
            #pragma unroll
            for (int mt = 0; mt < 2; mt++)
                #pragma unroll
                for (int nt = 0; nt < 8; nt++)
                    mma8(acc[mt][nt], am0[mt], am2[mt], am1[mt], am3[mt], b0[nt], b1[nt]);
        }
    }

    // ---- epilogue ----
    const int g = lane >> 2, c = lane & 3;
    #pragma unroll
    for (int mt = 0; mt < 2; mt++) {
        int row0 = bm + wm + mt * 16 + g;
        #pragma unroll
        for (int nt = 0; nt < 8; nt++) {
            int col0 = bn + wn + nt * 8 + 2 * c;
            float bi0 = bias[col0], bi1 = bias[col0 + 1];
            float v0 = acc[mt][nt][0] + bi0;
            float v1 = acc[mt][nt][1] + bi1;
            float v2 = acc[mt][nt][2] + bi0;
            float v3 = acc[mt][nt][3] + bi1;
            if (act == 1) {
                v0 = tf32r(gelu_tanh(v0));
                v1 = tf32r(gelu_tanh(v1));
                v2 = tf32r(gelu_tanh(v2));
                v3 = tf32r(gelu_tanh(v3));
            }
            *(float2*)&C[(size_t)row0 * N + col0]       = make_float2(v0, v1);
            *(float2*)&C[(size_t)(row0 + 8) * N + col0] = make_float2(v2, v3);
        }
    }
}

static inline void gemm_tc(const float* A, const float* BT, const float* bias, float* C,
                           int M, int K, int N, int act) {
    dim3 grid(N / 128, M / 128);
    gemm_tf32_kernel<<<grid, 256, GSMEM_BYTES>>>(A, BT, bias, C, M, K, N, act);
}

// ---------------- local windowed attention (rounds output: feeds proj GEMM) ----------------
__global__ void local_attn_kernel(const float* __restrict__ qkv,
                                  const float* __restrict__ rel,
                                  float* __restrict__ out)
{
    int blk = blockIdx.x;
    int h   = blk & (H_ - 1);
    int win = (blk >> 3) & (NW_ - 1);
    int b   = blk >> 10;
    int s0  = win * W_;
    int tid = threadIdx.x;

    __shared__ float ks[W_][HD_];
    __shared__ float vs[W_][HD_];

    size_t base = ((size_t)(b * S_ + s0)) * 1536 + h * HD_;
    for (int idx = tid; idx < W_ * HD_; idx += 32) {
        int jj = idx >> 6, d = idx & 63;
        ks[jj][d] = qkv[base + (size_t)jj * 1536 + 512 + d];
        vs[jj][d] = qkv[base + (size_t)jj * 1536 + 1024 + d];
    }
    __syncthreads();

    float q[HD_];
    {
        const float* qr = qkv + base + (size_t)tid * 1536;
        #pragma unroll
        for (int d = 0; d < HD_; d++) q[d] = qr[d];
    }

    float sc[W_];
    float m = -1e30f;
    #pragma unroll
    for (int jj = 0; jj < W_; jj++) {
        float a = 0.f;
        const float4* kj = (const float4*)ks[jj];
        #pragma unroll
        for (int d4 = 0; d4 < HD_ / 4; d4++) {
            float4 kk = kj[d4];
            a += q[4 * d4 + 0] * kk.x + q[4 * d4 + 1] * kk.y
               + q[4 * d4 + 2] * kk.z + q[4 * d4 + 3] * kk.w;
        }
        a = a * 0.125f + rel[(tid - jj + W_ - 1) * H_ + h];
        sc[jj] = a;
        m = fmaxf(m, a);
    }
    float sum = 0.f;
    #pragma unroll
    for (int jj = 0; jj < W_; jj++) { sc[jj] = expf(sc[jj] - m); sum += sc[jj]; }
    float inv = 1.f / sum;

    float o[HD_];
    #pragma unroll
    for (int d = 0; d < HD_; d++) o[d] = 0.f;
    #pragma unroll
    for (int jj = 0; jj < W_; jj++) {
        float p = sc[jj];
        const float4* vj = (const float4*)vs[jj];
        #pragma unroll
        for (int d4 = 0; d4 < HD_ / 4; d4++) {
            float4 vv = vj[d4];
            o[4 * d4 + 0] += p * vv.x;
            o[4 * d4 + 1] += p * vv.y;
            o[4 * d4 + 2] += p * vv.z;
            o[4 * d4 + 3] += p * vv.w;
        }
    }
    float* orow = out + (size_t)(b * S_ + s0 + tid) * D_ + h * HD_;
    #pragma unroll
    for (int d = 0; d < HD_; d++) orow[d] = tf32r(o[d] * inv);
}

// ---------------- global attention (rounds output: feeds proj GEMM) ----------------
__global__ void gattn_kernel(const float* __restrict__ qkv, float* __restrict__ out)
{
    int blk = blockIdx.x;
    int i = blk & (GS_ - 1);
    int h = (blk >> 7) & (H_ - 1);
    int b = blk >> 10;
    int tid = threadIdx.x;

    __shared__ float q[HD_];
    __shared__ float p[GS_];
    __shared__ float red[32];

    if (tid < HD_) q[tid] = qkv[(size_t)(b * GS_ + i) * 1536 + h * HD_ + tid];
    __syncthreads();

    float s;
    {
        const float* krow = qkv + (size_t)(b * GS_ + tid) * 1536 + 512 + h * HD_;
        float a = 0.f;
        #pragma unroll
        for (int d = 0; d < HD_; d++) a += q[d] * krow[d];
        s = a * 0.125f;
    }
    float m = blk_reduce_max(s, red);
    float e = expf(s - m);
    float sum = blk_reduce_sum(e, red);
    p[tid] = e;
    __syncthreads();

    if (tid < HD_) {
        float a = 0.f;
        for (int jj = 0; jj < GS_; jj++)
            a += p[jj] * qkv[(size_t)(b * GS_ + jj) * 1536 + 1024 + h * HD_ + tid];
        out[(size_t)(b * GS_ + i) * D_ + h * HD_ + tid] = tf32r(a / sum);
    }
}

// ---------------- fused residual add + LayerNorm (optional tf32 rounding) ----------------
__global__ void add_ln_kernel(const float* __restrict__ x, const float* __restrict__ a,
                              const float* __restrict__ g, const float* __restrict__ bb,
                              float* __restrict__ out, int round_out)
{
    __shared__ float red[32];
    size_t row = blockIdx.x;
    const float* xr = x + row * D_;
    const float* ar = a + row * D_;
    float v[4];
    float s = 0.f;
    #pragma unroll
    for (int i = 0; i < 4; i++) {
        int c = threadIdx.x + i * 128;
        v[i] = xr[c] + ar[c];
        s += v[i];
    }
    s = blk_reduce_sum(s, red);
    float mu = s * (1.f / D_);
    float s2 = 0.f;
    #pragma unroll
    for (int i = 0; i < 4; i++) { float d = v[i] - mu; s2 += d * d; }
    s2 = blk_reduce_sum(s2, red);
    float rstd = rsqrtf(s2 * (1.f / D_) + 1e-5f);
    #pragma unroll
    for (int i = 0; i < 4; i++) {
        int c = threadIdx.x + i * 128;
        float o = (v[i] - mu) * rstd * g[c] + bb[c];
        out[row * D_ + c] = round_out ? tf32r(o) : o;
    }
}

// ---------------- depthwise conv (K=7) + residual (rounds: feeds ffn1 GEMM) ----------------
__global__ void dwconv_kernel(const float* __restrict__ x, const float* __restrict__ w,
                              const float* __restrict__ cb, float* __restrict__ y)
{
    int idx = blockIdx.x * blockDim.x + threadIdx.x;
    if (idx >= M_ * D_) return;
    int d = idx & (D_ - 1);
    int s = (idx >> 9) & (S_ - 1);
    int b = idx >> 21;
    float acc = x[idx] + cb[d];
    #pragma unroll
    for (int k = 0; k < 7; k++) {
        int ss = s + k - 3;
        if (ss >= 0 && ss < S_)
            acc += w[d * 7 + k] * x[((size_t)(b * S_ + ss) << 9) + d];
    }
    y[idx] = tf32r(acc);
}

// ---------------- strided gather (stride 32), rounds (feeds qkv GEMM) ----------------
__global__ void gather_kernel(const float* __restrict__ src, float* __restrict__ dst)
{
    int idx = blockIdx.x * blockDim.x + threadIdx.x;
    if (idx >= GM_ * D_) return;
    int d = idx & (D_ - 1);
    int t = (idx >> 9) & (GS_ - 1);
    int b = idx >> 16;
    dst[idx] = tf32r(src[((size_t)(b * S_ + t * 32) << 9) + d]);
}

// ---------------- linear interp 128 -> 4096 ----------------
__global__ void interp_kernel(const float* __restrict__ a, float* __restrict__ out)
{
    int idx = blockIdx.x * blockDim.x + threadIdx.x;
    if (idx >= M_ * D_) return;
    int d = idx & (D_ - 1);
    int s = (idx >> 9) & (S_ - 1);
    int b = idx >> 21;
    float pos = (s + 0.5f) * (1.0f / 32.0f) - 0.5f;
    pos = fminf(fmaxf(pos, 0.0f), (float)(GS_ - 1));
    int i0 = (int)floorf(pos);
    int i1 = min(i0 + 1, GS_ - 1);
    float w = pos - (float)i0;
    float v0 = a[((size_t)(b * GS_ + i0) << 9) + d];
    float v1 = a[((size_t)(b * GS_ + i1) << 9) + d];
    out[idx] = v0 * (1.f - w) + v1 * w;
}

// ---------------- final weighted blend + LayerNorm ----------------
__global__ void final_kernel(const float* __restrict__ xl, const float* __restrict__ xg,
                             const float* __restrict__ pfl, const float* __restrict__ pfg,
                             const float* __restrict__ g, const float* __restrict__ bb,
                             float* __restrict__ out)
{
    __shared__ float red[32];
    float fl = *pfl, fg = *pfg;
    float mx = fmaxf(fl, fg);
    float e0 = expf(fl - mx), e1 = expf(fg - mx);
    float w0 = e0 / (e0 + e1), w1 = e1 / (e0 + e1);

    size_t row = blockIdx.x;
    const float* xr = xl + row * D_;
    const float* ar = xg + row * D_;
    float v[4];
    float s = 0.f;
    #pragma unroll
    for (int i = 0; i < 4; i++) {
        int c = threadIdx.x + i * 128;
        v[i] = w0 * xr[c] + w1 * ar[c];
        s += v[i];
    }
    s = blk_reduce_sum(s, red);
    float mu = s * (1.f / D_);
    float s2 = 0.f;
    #pragma unroll
    for (int i = 0; i < 4; i++) { float d = v[i] - mu; s2 += d * d; }
    s2 = blk_reduce_sum(s2, red);
    float rstd = rsqrtf(s2 * (1.f / D_) + 1e-5f);
    #pragma unroll
    for (int i = 0; i < 4; i++) {
        int c = threadIdx.x + i * 128;
        out[row * D_ + c] = (v[i] - mu) * rstd * g[c] + bb[c];
    }
}

// ---------------- host orchestration ----------------
static inline void transpose(const float* src, float* dst, int K, int N) {
    dim3 grid(N / 32, K / 32), blk(32, 8);
    transpose_kernel<<<grid, blk>>>(src, dst, K, N);
}

extern "C" void kernel_launch(void* const* d_in, const int* in_sizes, int n_in,
                              void* d_out, int out_size)
{
    const float* x       = (const float*)d_in[0];
    const float* lqkv_w  = (const float*)d_in[1];
    const float* lqkv_b  = (const float*)d_in[2];
    const float* lproj_w = (const float*)d_in[3];
    const float* lproj_b = (const float*)d_in[4];
    const float* lrel    = (const float*)d_in[5];
    const float* lconv_w = (const float*)d_in[6];
    const float* lconv_b = (const float*)d_in[7];
    const float* ln1_g   = (const float*)d_in[8];
    const float* ln1_b   = (const float*)d_in[9];
    const float* lffn_w1 = (const float*)d_in[10];
    const float* lffn_b1 = (const float*)d_in[11];
    const float* lffn_w2 = (const float*)d_in[12];
    const float* lffn_b2 = (const float*)d_in[13];
    const float* ln2_g   = (const float*)d_in[14];
    const float* ln2_b   = (const float*)d_in[15];
    const float* gqkv_w  = (const float*)d_in[16];
    const float* gqkv_b  = (const float*)d_in[17];
    const float* gproj_w = (const float*)d_in[18];
    const float* gproj_b = (const float*)d_in[19];
    const float* gn1_g   = (const float*)d_in[20];
    const float* gn1_b   = (const float*)d_in[21];
    const float* gffn_w1 = (const float*)d_in[22];
    const float* gffn_b1 = (const float*)d_in[23];
    const float* gffn_w2 = (const float*)d_in[24];
    const float* gffn_b2 = (const float*)d_in[25];
    const float* gn2_g   = (const float*)d_in[26];
    const float* gn2_b   = (const float*)d_in[27];
    const float* fw_l    = (const float*)d_in[28];
    const float* fw_g    = (const float*)d_in[29];
    const float* fn_g    = (const float*)d_in[30];
    const float* fn_b    = (const float*)d_in[31];

    float *xl, *xg, *xr, *tmp, *tmp2, *qkv, *hid, *xs, *atts, *ps;
    float *lqkvT, *lprojT, *lffn1T, *lffn2T, *gqkvT, *gprojT, *gffn1T, *gffn2T;
    cudaGetSymbolAddress((void**)&xl,   g_xl);
    cudaGetSymbolAddress((void**)&xg,   g_xg);
    cudaGetSymbolAddress((void**)&xr,   g_xr);
    cudaGetSymbolAddress((void**)&tmp,  g_tmp);
    cudaGetSymbolAddress((void**)&tmp2, g_tmp2);
    cudaGetSymbolAddress((void**)&qkv,  g_qkv);
    cudaGetSymbolAddress((void**)&hid,  g_hid);
    cudaGetSymbolAddress((void**)&xs,   g_xs);
    cudaGetSymbolAddress((void**)&atts, g_atts);
    cudaGetSymbolAddress((void**)&ps,   g_ps);
    cudaGetSymbolAddress((void**)&lqkvT,  g_lqkvT);
    cudaGetSymbolAddress((void**)&lprojT, g_lprojT);
    cudaGetSymbolAddress((void**)&lffn1T, g_lffn1T);
    cudaGetSymbolAddress((void**)&lffn2T, g_lffn2T);
    cudaGetSymbolAddress((void**)&gqkvT,  g_gqkvT);
    cudaGetSymbolAddress((void**)&gprojT, g_gprojT);
    cudaGetSymbolAddress((void**)&gffn1T, g_gffn1T);
    cudaGetSymbolAddress((void**)&gffn2T, g_gffn2T);

    cudaFuncSetAttribute(gemm_tf32_kernel,
                         cudaFuncAttributeMaxDynamicSharedMemorySize, GSMEM_BYTES);

    const int EW = 256;

    round_kernel<<<(M_ * D_ + EW - 1) / EW, EW>>>(x, xr, M_ * D_);

    // ---- local branch ----
    const float* asrc = xr;   // tf32-rounded GEMM A input
    const float* rsrc = x;    // exact residual input
    for (int i = 0; i < 4; i++) {
        transpose(lqkv_w  + (size_t)i * 512 * 1536, lqkvT  + (size_t)i * 1536 * 512, 512, 1536);
        transpose(lproj_w + (size_t)i * 512 * 512,  lprojT + (size_t)i * 512 * 512,  512, 512);
        transpose(lffn_w1 + (size_t)i * 512 * 2048, lffn1T + (size_t)i * 2048 * 512, 512, 2048);
        transpose(lffn_w2 + (size_t)i * 2048 * 512, lffn2T + (size_t)i * 512 * 2048, 2048, 512);

        gemm_tc(asrc, lqkvT + (size_t)i * 1536 * 512, lqkv_b + (size_t)i * 1536, qkv,
                M_, 512, 1536, 0);
        local_attn_kernel<<<B_ * NW_ * H_, 32>>>(qkv, lrel + (size_t)i * (2 * W_ - 1) * H_, tmp);
        gemm_tc(tmp, lprojT + (size_t)i * 512 * 512, lproj_b + (size_t)i * 512, tmp2,
                M_, 512, 512, 0);
        add_ln_kernel<<<M_, 128>>>(rsrc, tmp2, ln1_g + (size_t)i * D_, ln1_b + (size_t)i * D_,
                                   xl, 0);
        dwconv_kernel<<<(M_ * D_ + EW - 1) / EW, EW>>>(xl, lconv_w + (size_t)i * D_ * 7,
                                                        lconv_b + (size_t)i * D_, tmp);
        gemm_tc(tmp, lffn1T + (size_t)i * 2048 * 512, lffn_b1 + (size_t)i * 2048, hid,
                M_, 512, 2048, 1);
        gemm_tc(hid, lffn2T + (size_t)i * 512 * 2048, lffn_b2 + (size_t)i * 512, tmp2,
                M_, 2048, 512, 0);
        add_ln_kernel<<<M_, 128>>>(tmp, tmp2, ln2_g + (size_t)i * D_, ln2_b + (size_t)i * D_,
                                   xl, (i < 3) ? 1 : 0);
        asrc = xl;
        rsrc = xl;
    }

    // ---- global branch ----
    const float* gsrc = x;
    for (int i = 0; i < 3; i++) {
        transpose(gqkv_w  + (size_t)i * 512 * 1536, gqkvT  + (size_t)i * 1536 * 512, 512, 1536);
        transpose(gproj_w + (size_t)i * 512 * 512,  gprojT + (size_t)i * 512 * 512,  512, 512);
        transpose(gffn_w1 + (size_t)i * 512 * 2048, gffn1T + (size_t)i * 2048 * 512, 512, 2048);
        transpose(gffn_w2 + (size_t)i * 2048 * 512, gffn2T + (size_t)i * 512 * 2048, 2048, 512);

        gather_kernel<<<(GM_ * D_ + EW - 1) / EW, EW>>>(gsrc, xs);
        gemm_tc(xs, gqkvT + (size_t)i * 1536 * 512, gqkv_b + (size_t)i * 1536, qkv,
                GM_, 512, 1536, 0);
        gattn_kernel<<<B_ * H_ * GS_, 128>>>(qkv, atts);
        gemm_tc(atts, gprojT + (size_t)i * 512 * 512, gproj_b + (size_t)i * 512, ps,
                GM_, 512, 512, 0);
        interp_kernel<<<(M_ * D_ + EW - 1) / EW, EW>>>(ps, tmp);
        add_ln_kernel<<<M_, 128>>>(gsrc, tmp, gn1_g + (size_t)i * D_, gn1_b + (size_t)i * D_,
                                   xg, 1);
        gemm_tc(xg, gffn1T + (size_t)i * 2048 * 512, gffn_b1 + (size_t)i * 2048, hid,
                M_, 512, 2048, 1);
        gemm_tc(hid, gffn2T + (size_t)i * 512 * 2048, gffn_b2 + (size_t)i * 512, tmp2,
                M_, 2048, 512, 0);
        add_ln_kernel<<<M_, 128>>>(xg, tmp2, gn2_g + (size_t)i * D_, gn2_b + (size_t)i * D_,
                                   xg, 0);
        gsrc = xg;
    }

    // ---- final blend + LN ----
    final_kernel<<<M_, 128>>>(xl, xg, fw_l, fw_g, fn_g, fn_b, (float*)d_out);
}